// round 5
// baseline (speedup 1.0000x reference)
#include <cuda_runtime.h>
#include <cuda_bf16.h>
#include <cstdint>

#define NV 8192
#define DV 32
#define TV 12
#define RV 192   /* B*C*T = 2*8*12 */

typedef unsigned long long ull;

// ---------------- device scratch (no cudaMalloc anywhere) ----------------
__device__ float    g_core[DV * DV];
__device__ float    g_aT[DV * NV];                    // a transposed [f][n]
__device__ uint32_t g_Pth32[(size_t)NV * NV / 2];     // Pt hi bf16 pairs [m][n], 128MB
__device__ uint32_t g_Ptl32[(size_t)NV * NV / 2];     // Pt lo bf16 pairs, 128MB
__device__ uint32_t g_Bh32[NV * 96];                  // xs hi bf16 pairs [n][r]
__device__ uint32_t g_Bl32[NV * 96];                  // xs lo bf16 pairs [n][r]
__device__ float    g_cspart[64 * NV];                // column-sum partials per m-block
__device__ float    g_rinv[NV];                       // 1/rowsum
__device__ float    g_part2[2ULL * NV * RV];          // split-k partials fp32

// ---------------- f32x2 helpers ----------------
__device__ __forceinline__ ull pack2(float lo, float hi) {
    ull r; asm("mov.b64 %0, {%1,%2};" : "=l"(r) : "f"(lo), "f"(hi)); return r;
}
__device__ __forceinline__ void fma2(ull &acc, ull a, ull b) {
    asm("fma.rn.f32x2 %0, %1, %2, %0;" : "+l"(acc) : "l"(a), "l"(b));
}
__device__ __forceinline__ float2 unpack2(ull v) {
    float lo, hi; asm("mov.b64 {%0,%1}, %2;" : "=f"(lo), "=f"(hi) : "l"(v));
    return make_float2(lo, hi);
}

// ---------------- mma / ldmatrix / cp.async helpers (plain sm_80+ PTX) ----------------
__device__ __forceinline__ uint32_t smem_u32(const void* p) {
    uint32_t a;
    asm("{ .reg .u64 t; cvta.to.shared.u64 t, %1; cvt.u32.u64 %0, t; }" : "=r"(a) : "l"(p));
    return a;
}
__device__ __forceinline__ void ldsm_x4(uint32_t &r0, uint32_t &r1, uint32_t &r2, uint32_t &r3,
                                        uint32_t a) {
    asm volatile("ldmatrix.sync.aligned.m8n8.x4.shared.b16 {%0,%1,%2,%3}, [%4];"
                 : "=r"(r0), "=r"(r1), "=r"(r2), "=r"(r3) : "r"(a));
}
__device__ __forceinline__ void ldsm_x2t(uint32_t &r0, uint32_t &r1, uint32_t a) {
    asm volatile("ldmatrix.sync.aligned.m8n8.x2.trans.shared.b16 {%0,%1}, [%2];"
                 : "=r"(r0), "=r"(r1) : "r"(a));
}
__device__ __forceinline__ void mma16816(float* c, uint32_t a0, uint32_t a1, uint32_t a2,
                                         uint32_t a3, uint32_t b0, uint32_t b1) {
    asm volatile(
        "mma.sync.aligned.m16n8k16.row.col.f32.bf16.bf16.f32 "
        "{%0,%1,%2,%3}, {%4,%5,%6,%7}, {%8,%9}, {%0,%1,%2,%3};"
        : "+f"(c[0]), "+f"(c[1]), "+f"(c[2]), "+f"(c[3])
        : "r"(a0), "r"(a1), "r"(a2), "r"(a3), "r"(b0), "r"(b1));
}
__device__ __forceinline__ void cp16(uint32_t d, const void* s) {
    asm volatile("cp.async.cg.shared.global [%0], [%1], 16;" :: "r"(d), "l"(s) : "memory");
}

// ========== K1a: core[e][f] = sum_d tv[d]*k[d][e][f] ==========
__global__ void k_core(const float* __restrict__ timevec, const float* __restrict__ kk,
                       const int* __restrict__ tind) {
    int e = threadIdx.x >> 5, f = threadIdx.x & 31;
    int ti = tind[0];
    float s = 0.f;
#pragma unroll
    for (int d = 0; d < DV; ++d) s += timevec[ti * DV + d] * kk[(d * DV + e) * DV + f];
    g_core[e * DV + f] = s;
}

// ========== K1b: aT[f][n] = sum_e nv1[n][e]*core[e][f] ==========
__global__ void k_amat(const float* __restrict__ nv1) {
    __shared__ float sc[DV * DV];
    int tid = threadIdx.x;
    for (int i = tid; i < DV * DV; i += 256) sc[i] = g_core[i];
    __syncthreads();
    int n = blockIdx.x * 8 + (tid >> 5);
    int f = tid & 31;
    float s = 0.f;
#pragma unroll
    for (int e = 0; e < DV; ++e) s += nv1[n * DV + e] * sc[e * DV + f];
    g_aT[f * NV + n] = s;
}

// ========== K2: Pt[m][n] = exp(relu(nv2_m . a_n)) as bf16 hi/lo; colsum partials ==========
__global__ __launch_bounds__(256) void k_padj(const float* __restrict__ nv2) {
    __shared__ float sA[128 * 33];
    __shared__ ull   sB[32 * 66];
    __shared__ float red[16 * 132];

    int tid = threadIdx.x;
    int row0 = blockIdx.y * 128;
    int strip = blockIdx.x;
    for (int idx = tid; idx < 128 * 32; idx += 256) {
        int r = idx >> 5, c = idx & 31;
        sA[r * 33 + c] = nv2[(row0 + r) * DV + c];
    }
    int ty = tid >> 4, tx = tid & 15;

    for (int mc = 0; mc < 8; ++mc) {
        int n0c = strip * 1024 + mc * 128;
        __syncthreads();
        for (int idx = tid; idx < 32 * 64; idx += 256) {
            int k = idx >> 6, cp = idx & 63;
            sB[k * 66 + cp] = *(const ull*)&g_aT[k * NV + n0c + cp * 2];
        }
        __syncthreads();

        ull acc[8][4];
#pragma unroll
        for (int i = 0; i < 8; ++i)
#pragma unroll
            for (int j = 0; j < 4; ++j) acc[i][j] = 0ull;

#pragma unroll
        for (int k = 0; k < 32; ++k) {
            ull bv[4];
#pragma unroll
            for (int j = 0; j < 4; ++j) bv[j] = sB[k * 66 + j * 16 + tx];
#pragma unroll
            for (int i = 0; i < 8; ++i) {
                float av = sA[(ty * 8 + i) * 33 + k];
                ull a2 = pack2(av, av);
#pragma unroll
                for (int j = 0; j < 4; ++j) fma2(acc[i][j], a2, bv[j]);
            }
        }

        float rs0[4] = {0, 0, 0, 0}, rs1[4] = {0, 0, 0, 0};
#pragma unroll
        for (int i = 0; i < 8; ++i) {
            int m = row0 + ty * 8 + i;
#pragma unroll
            for (int j = 0; j < 4; ++j) {
                float2 h = unpack2(acc[i][j]);
                float p0 = __expf(fmaxf(h.x, 0.f));
                float p1 = __expf(fmaxf(h.y, 0.f));
                rs0[j] += p0; rs1[j] += p1;
                __nv_bfloat162 hh = __float22bfloat162_rn(make_float2(p0, p1));
                uint32_t hw = *(uint32_t*)&hh;
                float l0 = p0 - __uint_as_float(hw << 16);
                float l1 = p1 - __uint_as_float(hw & 0xFFFF0000u);
                __nv_bfloat162 lp = __float22bfloat162_rn(make_float2(l0, l1));
                size_t wi = ((size_t)m * NV + n0c + j * 32 + tx * 2) >> 1;
                g_Pth32[wi] = hw;
                g_Ptl32[wi] = *(uint32_t*)&lp;
            }
        }
#pragma unroll
        for (int j = 0; j < 4; ++j)
            *(float2*)&red[ty * 132 + j * 32 + tx * 2] = make_float2(rs0[j], rs1[j]);
        __syncthreads();
        if (tid < 128) {
            float s = 0.f;
#pragma unroll
            for (int q = 0; q < 16; ++q) s += red[q * 132 + tid];
            g_cspart[blockIdx.y * NV + n0c + tid] = s;
        }
    }
}

// ========== K2b: rowsum reduce (coalesced over n) ==========
__global__ void k_rsum() {
    int n = blockIdx.x * 256 + threadIdx.x;
    float s = 0.f;
#pragma unroll
    for (int mb = 0; mb < 64; ++mb) s += g_cspart[mb * NV + n];
    g_rinv[n] = 1.0f / s;
}

// ========== K3: B[n][r] = x[bc][n][t] * rinv[n] as bf16 hi/lo ==========
__global__ __launch_bounds__(96) void k_xs(const float* __restrict__ x) {
    int n = blockIdx.x;
    int tid = threadIdx.x;                // 0..95, r pair = (2t, 2t+1)
    float inv = g_rinv[n];
    int r0 = tid * 2;
    int bc = r0 / TV, t = r0 - bc * TV;   // t even -> t+1 in same bc
    const float* xp = x + ((size_t)bc * NV + n) * TV + t;
    float v0 = xp[0] * inv, v1 = xp[1] * inv;
    __nv_bfloat162 hh = __float22bfloat162_rn(make_float2(v0, v1));
    uint32_t hw = *(uint32_t*)&hh;
    float l0 = v0 - __uint_as_float(hw << 16);
    float l1 = v1 - __uint_as_float(hw & 0xFFFF0000u);
    __nv_bfloat162 lp = __float22bfloat162_rn(make_float2(l0, l1));
    g_Bh32[n * 96 + tid] = hw;
    g_Bl32[n * 96 + tid] = *(uint32_t*)&lp;
}

// ========== K4: warp-mma bf16 split GEMM  C[m][r] = sum_n Pt[m][n]*xs[n][r] ==========
// CTA: 128m x 192r, split-K 2 (4096 n each). 384 thr = 12 warps (2m x 6n).
// k-chunk 64, double-buffered cp.async. 3-product hi/lo split.
#define A_OFF_LO 16384
#define B_OFF    32768
#define B_STRIDE 400
#define B_OFF_LO 25600
#define BUFB     83968
#define SMEM_DYN (2 * BUFB)

__device__ __forceinline__ void gemm_loadbuf(uint32_t sbase, int buf, int i0, size_t kg,
                                             int tid) {
    uint32_t A = sbase + buf * BUFB;
    uint32_t B = A + B_OFF;
    const char* pa = (const char*)g_Pth32;
    const char* pl = (const char*)g_Ptl32;
#pragma unroll
    for (int l = 0; l < 6; ++l) {
        int idx = tid + l * 384;
        if (idx < 2048) {
            int half = idx >> 10, j = idx & 1023;
            int row = j >> 3, kb = j & 7;
            const char* src = (half ? pl : pa) + ((size_t)(i0 + row) * NV + kg + kb * 8) * 2;
            uint32_t dst = A + half * A_OFF_LO + row * 128 + ((kb ^ (row & 7)) << 4);
            cp16(dst, src);
        }
    }
    const char* bh = (const char*)g_Bh32;
    const char* bl = (const char*)g_Bl32;
#pragma unroll
    for (int l = 0; l < 8; ++l) {
        int idx = tid + l * 384;
        int half = idx >= 1536;
        int j = half ? idx - 1536 : idx;
        int kr = j / 24, cb = j % 24;
        const char* src = (half ? bl : bh) + (kg + kr) * 384 + cb * 16;
        uint32_t dst = B + half * B_OFF_LO + kr * B_STRIDE + cb * 16;
        cp16(dst, src);
    }
    asm volatile("cp.async.commit_group;" ::: "memory");
}

__global__ __launch_bounds__(384, 1) void k_gemm3() {
    extern __shared__ char sm[];
    uint32_t sbase = smem_u32(sm);
    const int tid = threadIdx.x, lane = tid & 31, wid = tid >> 5;
    const int wm = wid & 1;          // 64-row half
    const int wn = wid >> 1;         // 0..5 -> 32-col slice
    const int i0 = blockIdx.x * 128;
    const size_t k0 = (size_t)blockIdx.y * 4096;

    float acc[4][4][4];
#pragma unroll
    for (int mt = 0; mt < 4; ++mt)
#pragma unroll
        for (int nt = 0; nt < 4; ++nt)
#pragma unroll
            for (int q = 0; q < 4; ++q) acc[mt][nt][q] = 0.f;

    gemm_loadbuf(sbase, 0, i0, k0, tid);

    for (int c = 0; c < 64; ++c) {
        int buf = c & 1;
        if (c + 1 < 64) {
            gemm_loadbuf(sbase, buf ^ 1, i0, k0 + (size_t)(c + 1) * 64, tid);
            asm volatile("cp.async.wait_group 1;" ::: "memory");
        } else {
            asm volatile("cp.async.wait_group 0;" ::: "memory");
        }
        __syncthreads();

        uint32_t A = sbase + buf * BUFB;
        uint32_t B = A + B_OFF;
#pragma unroll
        for (int ks = 0; ks < 4; ++ks) {
            uint32_t bh[4][2], blo[4][2];
            int krow = ks * 16 + (lane & 15);
#pragma unroll
            for (int nt = 0; nt < 4; ++nt) {
                uint32_t ba = B + krow * B_STRIDE + (wn * 32 + nt * 8) * 2;
                ldsm_x2t(bh[nt][0], bh[nt][1], ba);
                ldsm_x2t(blo[nt][0], blo[nt][1], ba + B_OFF_LO);
            }
            int row = wm * 64 + (lane & 15);
            int kb = ks * 2 + (lane >> 4);
#pragma unroll
            for (int mt = 0; mt < 4; ++mt) {
                int rr = row + mt * 16;
                uint32_t aa = A + rr * 128 + ((kb ^ (rr & 7)) << 4);
                uint32_t ah0, ah1, ah2, ah3, al0, al1, al2, al3;
                ldsm_x4(ah0, ah1, ah2, ah3, aa);
                ldsm_x4(al0, al1, al2, al3, aa + A_OFF_LO);
#pragma unroll
                for (int nt = 0; nt < 4; ++nt) {
                    mma16816(acc[mt][nt], ah0, ah1, ah2, ah3, bh[nt][0], bh[nt][1]);
                    mma16816(acc[mt][nt], ah0, ah1, ah2, ah3, blo[nt][0], blo[nt][1]);
                    mma16816(acc[mt][nt], al0, al1, al2, al3, bh[nt][0], bh[nt][1]);
                }
            }
        }
        __syncthreads();
    }

    float* outp = g_part2 + (size_t)blockIdx.y * NV * RV;
#pragma unroll
    for (int mt = 0; mt < 4; ++mt) {
#pragma unroll
        for (int nt = 0; nt < 4; ++nt) {
            int m = i0 + wm * 64 + mt * 16 + (lane >> 2);
            int r = wn * 32 + nt * 8 + (lane & 3) * 2;
            *(float2*)&outp[(size_t)m * RV + r] = make_float2(acc[mt][nt][0], acc[mt][nt][1]);
            *(float2*)&outp[(size_t)(m + 8) * RV + r] = make_float2(acc[mt][nt][2], acc[mt][nt][3]);
        }
    }
}

// ========== K5: reduce 2 split-K partials, scatter to out[b][c][m][t] ==========
__global__ void k_out2(float* __restrict__ out) {
    int idx = blockIdx.x * 256 + threadIdx.x;
    if (idx >= NV * RV) return;
    int m = idx / RV, r = idx - m * RV;
    float v = g_part2[idx] + g_part2[(size_t)NV * RV + idx];
    int bc = r / TV, t = r - bc * TV;
    out[((size_t)bc * NV + m) * TV + t] = v;
}

extern "C" void kernel_launch(void* const* d_in, const int* in_sizes, int n_in,
                              void* d_out, int out_size) {
    const float* x    = (const float*)d_in[0];
    const float* nv1  = (const float*)d_in[1];
    const float* nv2  = (const float*)d_in[2];
    const float* tvv  = (const float*)d_in[3];
    const float* kk   = (const float*)d_in[4];
    const int*   tind = (const int*)d_in[5];
    float* out = (float*)d_out;

    cudaFuncSetAttribute(k_gemm3, cudaFuncAttributeMaxDynamicSharedMemorySize, SMEM_DYN);

    k_core<<<1, 1024>>>(tvv, kk, tind);
    k_amat<<<NV / 8, 256>>>(nv1);
    k_padj<<<dim3(8, 64), 256>>>(nv2);
    k_rsum<<<NV / 256, 256>>>();
    k_xs<<<NV, 96>>>(x);
    k_gemm3<<<dim3(64, 2), 384, SMEM_DYN>>>();
    k_out2<<<(NV * RV + 255) / 256, 256>>>(out);
}

// round 6
// speedup vs baseline: 1.3146x; 1.3146x over previous
#include <cuda_runtime.h>
#include <cuda_bf16.h>
#include <cstdint>

#define NV 8192
#define DV 32
#define TV 12
#define RV 192   /* B*C*T = 2*8*12 */

typedef unsigned long long ull;

// ---------------- device scratch (no cudaMalloc anywhere) ----------------
__device__ float    g_core[DV * DV];
__device__ float    g_aT[DV * NV];                    // a transposed [f][n]
__device__ __nv_bfloat16 g_A2h[NV * DV];              // nv2 hi bf16 [m][k]
__device__ __nv_bfloat16 g_A2l[NV * DV];              // nv2 lo
__device__ __nv_bfloat16 g_aTh[DV * NV];              // aT hi bf16 [k][n]
__device__ __nv_bfloat16 g_aTl[DV * NV];              // aT lo
__device__ uint32_t g_Pth32[(size_t)NV * NV / 2];     // Pt hi bf16 pairs [m][n], 128MB
__device__ uint32_t g_Ptl32[(size_t)NV * NV / 2];     // Pt lo bf16 pairs, 128MB
__device__ uint32_t g_Bh32[NV * 96];                  // xs hi bf16 pairs [n][r]
__device__ uint32_t g_Bl32[NV * 96];                  // xs lo bf16 pairs [n][r]
__device__ float    g_cspart[64 * NV];                // column-sum partials per m-block
__device__ float    g_rinv[NV];                       // 1/rowsum
__device__ float    g_part2[2ULL * NV * RV];          // split-k partials fp32

// ---------------- mma / ldmatrix / cp.async helpers (plain sm_80+ PTX) ----------------
__device__ __forceinline__ uint32_t smem_u32(const void* p) {
    uint32_t a;
    asm("{ .reg .u64 t; cvta.to.shared.u64 t, %1; cvt.u32.u64 %0, t; }" : "=r"(a) : "l"(p));
    return a;
}
__device__ __forceinline__ void ldsm_x4(uint32_t &r0, uint32_t &r1, uint32_t &r2, uint32_t &r3,
                                        uint32_t a) {
    asm volatile("ldmatrix.sync.aligned.m8n8.x4.shared.b16 {%0,%1,%2,%3}, [%4];"
                 : "=r"(r0), "=r"(r1), "=r"(r2), "=r"(r3) : "r"(a));
}
__device__ __forceinline__ void ldsm_x2t(uint32_t &r0, uint32_t &r1, uint32_t a) {
    asm volatile("ldmatrix.sync.aligned.m8n8.x2.trans.shared.b16 {%0,%1}, [%2];"
                 : "=r"(r0), "=r"(r1) : "r"(a));
}
__device__ __forceinline__ void mma16816(float* c, uint32_t a0, uint32_t a1, uint32_t a2,
                                         uint32_t a3, uint32_t b0, uint32_t b1) {
    asm volatile(
        "mma.sync.aligned.m16n8k16.row.col.f32.bf16.bf16.f32 "
        "{%0,%1,%2,%3}, {%4,%5,%6,%7}, {%8,%9}, {%0,%1,%2,%3};"
        : "+f"(c[0]), "+f"(c[1]), "+f"(c[2]), "+f"(c[3])
        : "r"(a0), "r"(a1), "r"(a2), "r"(a3), "r"(b0), "r"(b1));
}
__device__ __forceinline__ void cp16(uint32_t d, const void* s) {
    asm volatile("cp.async.cg.shared.global [%0], [%1], 16;" :: "r"(d), "l"(s) : "memory");
}

// ========== K1a: core[e][f] = sum_d tv[d]*k[d][e][f] ==========
__global__ void k_core(const float* __restrict__ timevec, const float* __restrict__ kk,
                       const int* __restrict__ tind) {
    int e = threadIdx.x >> 5, f = threadIdx.x & 31;
    int ti = tind[0];
    float s = 0.f;
#pragma unroll
    for (int d = 0; d < DV; ++d) s += timevec[ti * DV + d] * kk[(d * DV + e) * DV + f];
    g_core[e * DV + f] = s;
}

// ========== K1b: aT[f][n] = sum_e nv1[n][e]*core[e][f] ==========
__global__ void k_amat(const float* __restrict__ nv1) {
    __shared__ float sc[DV * DV];
    int tid = threadIdx.x;
    for (int i = tid; i < DV * DV; i += 256) sc[i] = g_core[i];
    __syncthreads();
    int n = blockIdx.x * 8 + (tid >> 5);
    int f = tid & 31;
    float s = 0.f;
#pragma unroll
    for (int e = 0; e < DV; ++e) s += nv1[n * DV + e] * sc[e * DV + f];
    g_aT[f * NV + n] = s;
}

// ========== K1c: bf16 hi/lo pre-split of nv2 and aT ==========
__global__ void k_split(const float* __restrict__ nv2) {
    int idx = blockIdx.x * 256 + threadIdx.x;   // 0 .. 2*NV*DV-1
    if (idx < NV * DV) {
        float v = nv2[idx];
        __nv_bfloat16 h = __float2bfloat16_rn(v);
        g_A2h[idx] = h;
        g_A2l[idx] = __float2bfloat16_rn(v - __bfloat162float(h));
    } else {
        int j = idx - NV * DV;
        float v = g_aT[j];
        __nv_bfloat16 h = __float2bfloat16_rn(v);
        g_aTh[j] = h;
        g_aTl[j] = __float2bfloat16_rn(v - __bfloat162float(h));
    }
}

// ========== K2: HMMA logit GEMM + exp + hi/lo split + colsum ==========
// grid (64 nblk, 64 mblk), CTA 128m x 128n, 256 thr = 8 warps (wm 2 x wn 4).
#define PJ_AH 0
#define PJ_AL 16384
#define PJ_BH 32768
#define PJ_BL 41472
#define PJ_STH 0            /* stage reuses operand region after sync */
#define PJ_STL 34816
#define PJ_RED 69632
#define PJ_SMEM (69632 + 8448)

__global__ __launch_bounds__(256) void k_padj_mma() {
    extern __shared__ char sm[];
    uint32_t sb = smem_u32(sm);
    const int tid = threadIdx.x, lane = tid & 31, wid = tid >> 5;
    const int wm = wid & 1;            // 64-row half
    const int wn = wid >> 1;           // 0..3 -> 32-col slice
    const int n0 = blockIdx.x * 128;
    const int i0 = blockIdx.y * 128;

    // ---- load A (nv2 rows, hi/lo) with slot swizzle; B (aT rows) stride 272 ----
#pragma unroll
    for (int l = 0; l < 4; ++l) {
        int idx = tid + l * 256;       // 1024 = 2 halves x 128 rows x 4 chunks
        int half = idx >> 9, j = idx & 511;
        int r = j >> 2, kb = j & 3;
        const __nv_bfloat16* src = (half ? g_A2l : g_A2h) + (size_t)(i0 + r) * DV + kb * 8;
        uint32_t slot = (uint32_t)((kb ^ (r & 3)) | (r & 4));
        cp16(sb + (half ? PJ_AL : PJ_AH) + r * 128 + slot * 16, src);
    }
#pragma unroll
    for (int l = 0; l < 4; ++l) {
        int idx = tid + l * 256;       // 1024 = 2 halves x 32 rows x 16 chunks
        int half = idx >> 9, j = idx & 511;
        int kr = j >> 4, cb = j & 15;
        const __nv_bfloat16* src = (half ? g_aTl : g_aTh) + (size_t)kr * NV + n0 + cb * 8;
        cp16(sb + (half ? PJ_BL : PJ_BH) + kr * 272 + cb * 16, src);
    }
    asm volatile("cp.async.commit_group;" ::: "memory");
    asm volatile("cp.async.wait_group 0;" ::: "memory");
    __syncthreads();

    float acc[4][4][4];
#pragma unroll
    for (int mt = 0; mt < 4; ++mt)
#pragma unroll
        for (int nt = 0; nt < 4; ++nt)
#pragma unroll
            for (int q = 0; q < 4; ++q) acc[mt][nt][q] = 0.f;

#pragma unroll
    for (int ks = 0; ks < 2; ++ks) {
        uint32_t bh[4][2], bl[4][2];
        int krow = ks * 16 + (lane & 15);
#pragma unroll
        for (int nt = 0; nt < 4; ++nt) {
            uint32_t ba = sb + PJ_BH + krow * 272 + (wn * 32 + nt * 8) * 2;
            ldsm_x2t(bh[nt][0], bh[nt][1], ba);
            ldsm_x2t(bl[nt][0], bl[nt][1], ba + (PJ_BL - PJ_BH));
        }
        int kb = ks * 2 + (lane >> 4);
#pragma unroll
        for (int mt = 0; mt < 4; ++mt) {
            int rr = wm * 64 + mt * 16 + (lane & 15);
            uint32_t slot = (uint32_t)((kb ^ (rr & 3)) | (rr & 4));
            uint32_t aa = sb + PJ_AH + rr * 128 + slot * 16;
            uint32_t ah0, ah1, ah2, ah3, al0, al1, al2, al3;
            ldsm_x4(ah0, ah1, ah2, ah3, aa);
            ldsm_x4(al0, al1, al2, al3, aa + (PJ_AL - PJ_AH));
#pragma unroll
            for (int nt = 0; nt < 4; ++nt) {
                mma16816(acc[mt][nt], ah0, ah1, ah2, ah3, bh[nt][0], bh[nt][1]);
                mma16816(acc[mt][nt], ah0, ah1, ah2, ah3, bl[nt][0], bl[nt][1]);
                mma16816(acc[mt][nt], al0, al1, al2, al3, bh[nt][0], bh[nt][1]);
            }
        }
    }
    __syncthreads();   // all warps done reading operands; stage region reuses them

    // ---- epilogue: exp, split, stage to smem, colsum partials ----
    uint32_t* sth = (uint32_t*)(sm + PJ_STH);
    uint32_t* stl = (uint32_t*)(sm + PJ_STL);
    float* red = (float*)(sm + PJ_RED);
    int slot = wm * 8 + (lane >> 2);
    int npb = wn * 16 + (lane & 3);            // word-col base within 64 (+ nt*4)
#pragma unroll
    for (int nt = 0; nt < 4; ++nt) {
        float se = 0.f, so = 0.f;
        int np = npb + nt * 4;
#pragma unroll
        for (int mt = 0; mt < 4; ++mt) {
            float* c = acc[mt][nt];
            int mlo = wm * 64 + mt * 16 + (lane >> 2);
            float p0 = __expf(fmaxf(c[0], 0.f));
            float p1 = __expf(fmaxf(c[1], 0.f));
            float p2 = __expf(fmaxf(c[2], 0.f));
            float p3 = __expf(fmaxf(c[3], 0.f));
            se += p0 + p2; so += p1 + p3;
            __nv_bfloat162 h01 = __float22bfloat162_rn(make_float2(p0, p1));
            __nv_bfloat162 h23 = __float22bfloat162_rn(make_float2(p2, p3));
            uint32_t w01 = *(uint32_t*)&h01, w23 = *(uint32_t*)&h23;
            float l0 = p0 - __uint_as_float(w01 << 16);
            float l1 = p1 - __uint_as_float(w01 & 0xFFFF0000u);
            float l2 = p2 - __uint_as_float(w23 << 16);
            float l3 = p3 - __uint_as_float(w23 & 0xFFFF0000u);
            __nv_bfloat162 lo01 = __float22bfloat162_rn(make_float2(l0, l1));
            __nv_bfloat162 lo23 = __float22bfloat162_rn(make_float2(l2, l3));
            sth[mlo * 68 + np] = w01;
            sth[(mlo + 8) * 68 + np] = w23;
            stl[mlo * 68 + np] = *(uint32_t*)&lo01;
            stl[(mlo + 8) * 68 + np] = *(uint32_t*)&lo23;
        }
        *(float2*)&red[slot * 132 + wn * 32 + nt * 8 + (lane & 3) * 2] = make_float2(se, so);
    }
    __syncthreads();

    // ---- coalesced copy-out (uint4) + colsum reduce ----
    size_t wbase = (size_t)i0 * (NV / 2) + (n0 >> 1);
#pragma unroll
    for (int it = 0; it < 8; ++it) {
        int idx = tid + it * 256;      // 2048 uint4 per half
        int row = idx >> 4, cb = idx & 15;
        uint4 vh = *(uint4*)&sth[row * 68 + cb * 4];
        uint4 vl = *(uint4*)&stl[row * 68 + cb * 4];
        *(uint4*)&g_Pth32[wbase + (size_t)row * (NV / 2) + cb * 4] = vh;
        *(uint4*)&g_Ptl32[wbase + (size_t)row * (NV / 2) + cb * 4] = vl;
    }
    if (tid < 128) {
        float s = 0.f;
#pragma unroll
        for (int q = 0; q < 16; ++q) s += red[q * 132 + tid];
        g_cspart[blockIdx.y * NV + n0 + tid] = s;
    }
}

// ========== K2b: rowsum reduce ==========
__global__ void k_rsum() {
    int n = blockIdx.x * 256 + threadIdx.x;
    float s = 0.f;
#pragma unroll
    for (int mb = 0; mb < 64; ++mb) s += g_cspart[mb * NV + n];
    g_rinv[n] = 1.0f / s;
}

// ========== K3: B[n][r] = x[bc][n][t] * rinv[n] as bf16 hi/lo ==========
__global__ __launch_bounds__(96) void k_xs(const float* __restrict__ x) {
    int n = blockIdx.x;
    int tid = threadIdx.x;
    float inv = g_rinv[n];
    int r0 = tid * 2;
    int bc = r0 / TV, t = r0 - bc * TV;
    const float* xp = x + ((size_t)bc * NV + n) * TV + t;
    float v0 = xp[0] * inv, v1 = xp[1] * inv;
    __nv_bfloat162 hh = __float22bfloat162_rn(make_float2(v0, v1));
    uint32_t hw = *(uint32_t*)&hh;
    float l0 = v0 - __uint_as_float(hw << 16);
    float l1 = v1 - __uint_as_float(hw & 0xFFFF0000u);
    __nv_bfloat162 lp = __float22bfloat162_rn(make_float2(l0, l1));
    g_Bh32[n * 96 + tid] = hw;
    g_Bl32[n * 96 + tid] = *(uint32_t*)&lp;
}

// ========== K4: warp-mma bf16 split GEMM  C[m][r] = sum_n Pt[m][n]*xs[n][r] ==========
#define A_OFF_LO 16384
#define B_OFF    32768
#define B_STRIDE 400
#define B_OFF_LO 25600
#define BUFB     83968
#define SMEM_DYN (2 * BUFB)

__device__ __forceinline__ void gemm_loadbuf(uint32_t sbase, int buf, int i0, size_t kg,
                                             int tid) {
    uint32_t A = sbase + buf * BUFB;
    uint32_t B = A + B_OFF;
    const char* pa = (const char*)g_Pth32;
    const char* pl = (const char*)g_Ptl32;
#pragma unroll
    for (int l = 0; l < 6; ++l) {
        int idx = tid + l * 384;
        if (idx < 2048) {
            int half = idx >> 10, j = idx & 1023;
            int row = j >> 3, kb = j & 7;
            const char* src = (half ? pl : pa) + ((size_t)(i0 + row) * NV + kg + kb * 8) * 2;
            uint32_t dst = A + half * A_OFF_LO + row * 128 + ((kb ^ (row & 7)) << 4);
            cp16(dst, src);
        }
    }
    const char* bh = (const char*)g_Bh32;
    const char* bl = (const char*)g_Bl32;
#pragma unroll
    for (int l = 0; l < 8; ++l) {
        int idx = tid + l * 384;
        int half = idx >= 1536;
        int j = half ? idx - 1536 : idx;
        int kr = j / 24, cb = j % 24;
        const char* src = (half ? bl : bh) + (kg + kr) * 384 + cb * 16;
        uint32_t dst = B + half * B_OFF_LO + kr * B_STRIDE + cb * 16;
        cp16(dst, src);
    }
    asm volatile("cp.async.commit_group;" ::: "memory");
}

__global__ __launch_bounds__(384, 1) void k_gemm3() {
    extern __shared__ char sm[];
    uint32_t sbase = smem_u32(sm);
    const int tid = threadIdx.x, lane = tid & 31, wid = tid >> 5;
    const int wm = wid & 1;
    const int wn = wid >> 1;
    const int i0 = blockIdx.x * 128;
    const size_t k0 = (size_t)blockIdx.y * 4096;

    float acc[4][4][4];
#pragma unroll
    for (int mt = 0; mt < 4; ++mt)
#pragma unroll
        for (int nt = 0; nt < 4; ++nt)
#pragma unroll
            for (int q = 0; q < 4; ++q) acc[mt][nt][q] = 0.f;

    gemm_loadbuf(sbase, 0, i0, k0, tid);

    for (int c = 0; c < 64; ++c) {
        int buf = c & 1;
        if (c + 1 < 64) {
            gemm_loadbuf(sbase, buf ^ 1, i0, k0 + (size_t)(c + 1) * 64, tid);
            asm volatile("cp.async.wait_group 1;" ::: "memory");
        } else {
            asm volatile("cp.async.wait_group 0;" ::: "memory");
        }
        __syncthreads();

        uint32_t A = sbase + buf * BUFB;
        uint32_t B = A + B_OFF;
#pragma unroll
        for (int ks = 0; ks < 4; ++ks) {
            uint32_t bh[4][2], blo[4][2];
            int krow = ks * 16 + (lane & 15);
#pragma unroll
            for (int nt = 0; nt < 4; ++nt) {
                uint32_t ba = B + krow * B_STRIDE + (wn * 32 + nt * 8) * 2;
                ldsm_x2t(bh[nt][0], bh[nt][1], ba);
                ldsm_x2t(blo[nt][0], blo[nt][1], ba + B_OFF_LO);
            }
            int row = wm * 64 + (lane & 15);
            int kb = ks * 2 + (lane >> 4);
#pragma unroll
            for (int mt = 0; mt < 4; ++mt) {
                int rr = row + mt * 16;
                uint32_t aa = A + rr * 128 + ((kb ^ (rr & 7)) << 4);
                uint32_t ah0, ah1, ah2, ah3, al0, al1, al2, al3;
                ldsm_x4(ah0, ah1, ah2, ah3, aa);
                ldsm_x4(al0, al1, al2, al3, aa + A_OFF_LO);
#pragma unroll
                for (int nt = 0; nt < 4; ++nt) {
                    mma16816(acc[mt][nt], ah0, ah1, ah2, ah3, bh[nt][0], bh[nt][1]);
                    mma16816(acc[mt][nt], ah0, ah1, ah2, ah3, blo[nt][0], blo[nt][1]);
                    mma16816(acc[mt][nt], al0, al1, al2, al3, bh[nt][0], bh[nt][1]);
                }
            }
        }
        __syncthreads();
    }

    float* outp = g_part2 + (size_t)blockIdx.y * NV * RV;
#pragma unroll
    for (int mt = 0; mt < 4; ++mt) {
#pragma unroll
        for (int nt = 0; nt < 4; ++nt) {
            int m = i0 + wm * 64 + mt * 16 + (lane >> 2);
            int r = wn * 32 + nt * 8 + (lane & 3) * 2;
            *(float2*)&outp[(size_t)m * RV + r] = make_float2(acc[mt][nt][0], acc[mt][nt][1]);
            *(float2*)&outp[(size_t)(m + 8) * RV + r] = make_float2(acc[mt][nt][2], acc[mt][nt][3]);
        }
    }
}

// ========== K5: reduce 2 split-K partials, scatter to out[b][c][m][t] ==========
__global__ void k_out2(float* __restrict__ out) {
    int idx = blockIdx.x * 256 + threadIdx.x;
    if (idx >= NV * RV) return;
    int m = idx / RV, r = idx - m * RV;
    float v = g_part2[idx] + g_part2[(size_t)NV * RV + idx];
    int bc = r / TV, t = r - bc * TV;
    out[((size_t)bc * NV + m) * TV + t] = v;
}

extern "C" void kernel_launch(void* const* d_in, const int* in_sizes, int n_in,
                              void* d_out, int out_size) {
    const float* x    = (const float*)d_in[0];
    const float* nv1  = (const float*)d_in[1];
    const float* nv2  = (const float*)d_in[2];
    const float* tvv  = (const float*)d_in[3];
    const float* kk   = (const float*)d_in[4];
    const int*   tind = (const int*)d_in[5];
    float* out = (float*)d_out;

    cudaFuncSetAttribute(k_gemm3, cudaFuncAttributeMaxDynamicSharedMemorySize, SMEM_DYN);
    cudaFuncSetAttribute(k_padj_mma, cudaFuncAttributeMaxDynamicSharedMemorySize, PJ_SMEM);

    k_core<<<1, 1024>>>(tvv, kk, tind);
    k_amat<<<NV / 8, 256>>>(nv1);
    k_split<<<2 * NV * DV / 256, 256>>>(nv2);
    k_padj_mma<<<dim3(64, 64), 256, PJ_SMEM>>>();
    k_rsum<<<NV / 256, 256>>>();
    k_xs<<<NV, 96>>>(x);
    k_gemm3<<<dim3(64, 2), 384, SMEM_DYN>>>();
    k_out2<<<(NV * RV + 255) / 256, 256>>>(out);
}

// round 7
// speedup vs baseline: 1.6785x; 1.2769x over previous
#include <cuda_runtime.h>
#include <cuda_bf16.h>
#include <cuda_fp16.h>
#include <cstdint>

#define NV 8192
#define DV 32
#define TV 12
#define RV 192   /* B*C*T = 2*8*12 */

typedef unsigned long long ull;

// ---------------- device scratch (no cudaMalloc anywhere) ----------------
__device__ float    g_core[DV * DV];
__device__ float    g_aT[DV * NV];                    // a transposed [f][n]
__device__ __nv_bfloat16 g_A2h[NV * DV];              // nv2 hi bf16 [m][k]
__device__ __nv_bfloat16 g_A2l[NV * DV];              // nv2 lo
__device__ __nv_bfloat16 g_aTh[DV * NV];              // aT hi bf16 [k][n]
__device__ __nv_bfloat16 g_aTl[DV * NV];              // aT lo
__device__ uint32_t g_Ph32[(size_t)NV * NV / 2];      // Pt fp16 pairs [m][n], 128MB
__device__ uint32_t g_Bh32[NV * 96];                  // xs hi fp16 pairs [n][r] (x4096)
__device__ uint32_t g_Bl32[NV * 96];                  // xs lo fp16 pairs [n][r]
__device__ float    g_cspart[64 * NV];                // column-sum partials per m-block
__device__ float    g_rinv[NV];                       // 4096/rowsum
__device__ float    g_part2[2ULL * NV * RV];          // split-k partials fp32

// ---------------- mma / ldmatrix / cp.async helpers (plain sm_80+ PTX) ----------------
__device__ __forceinline__ uint32_t smem_u32(const void* p) {
    uint32_t a;
    asm("{ .reg .u64 t; cvta.to.shared.u64 t, %1; cvt.u32.u64 %0, t; }" : "=r"(a) : "l"(p));
    return a;
}
__device__ __forceinline__ void ldsm_x4(uint32_t &r0, uint32_t &r1, uint32_t &r2, uint32_t &r3,
                                        uint32_t a) {
    asm volatile("ldmatrix.sync.aligned.m8n8.x4.shared.b16 {%0,%1,%2,%3}, [%4];"
                 : "=r"(r0), "=r"(r1), "=r"(r2), "=r"(r3) : "r"(a));
}
__device__ __forceinline__ void ldsm_x4t(uint32_t &r0, uint32_t &r1, uint32_t &r2, uint32_t &r3,
                                         uint32_t a) {
    asm volatile("ldmatrix.sync.aligned.m8n8.x4.trans.shared.b16 {%0,%1,%2,%3}, [%4];"
                 : "=r"(r0), "=r"(r1), "=r"(r2), "=r"(r3) : "r"(a));
}
__device__ __forceinline__ void ldsm_x2t(uint32_t &r0, uint32_t &r1, uint32_t a) {
    asm volatile("ldmatrix.sync.aligned.m8n8.x2.trans.shared.b16 {%0,%1}, [%2];"
                 : "=r"(r0), "=r"(r1) : "r"(a));
}
__device__ __forceinline__ void mma16816(float* c, uint32_t a0, uint32_t a1, uint32_t a2,
                                         uint32_t a3, uint32_t b0, uint32_t b1) {
    asm volatile(
        "mma.sync.aligned.m16n8k16.row.col.f32.bf16.bf16.f32 "
        "{%0,%1,%2,%3}, {%4,%5,%6,%7}, {%8,%9}, {%0,%1,%2,%3};"
        : "+f"(c[0]), "+f"(c[1]), "+f"(c[2]), "+f"(c[3])
        : "r"(a0), "r"(a1), "r"(a2), "r"(a3), "r"(b0), "r"(b1));
}
__device__ __forceinline__ void mma16816h(float* c, uint32_t a0, uint32_t a1, uint32_t a2,
                                          uint32_t a3, uint32_t b0, uint32_t b1) {
    asm volatile(
        "mma.sync.aligned.m16n8k16.row.col.f32.f16.f16.f32 "
        "{%0,%1,%2,%3}, {%4,%5,%6,%7}, {%8,%9}, {%0,%1,%2,%3};"
        : "+f"(c[0]), "+f"(c[1]), "+f"(c[2]), "+f"(c[3])
        : "r"(a0), "r"(a1), "r"(a2), "r"(a3), "r"(b0), "r"(b1));
}
__device__ __forceinline__ void cp16(uint32_t d, const void* s) {
    asm volatile("cp.async.cg.shared.global [%0], [%1], 16;" :: "r"(d), "l"(s) : "memory");
}

// ========== K1a: core[e][f] = sum_d tv[d]*k[d][e][f] ==========
__global__ void k_core(const float* __restrict__ timevec, const float* __restrict__ kk,
                       const int* __restrict__ tind) {
    int e = threadIdx.x >> 5, f = threadIdx.x & 31;
    int ti = tind[0];
    float s = 0.f;
#pragma unroll
    for (int d = 0; d < DV; ++d) s += timevec[ti * DV + d] * kk[(d * DV + e) * DV + f];
    g_core[e * DV + f] = s;
}

// ========== K1b: aT[f][n] = sum_e nv1[n][e]*core[e][f] ==========
__global__ void k_amat(const float* __restrict__ nv1) {
    __shared__ float sc[DV * DV];
    int tid = threadIdx.x;
    for (int i = tid; i < DV * DV; i += 256) sc[i] = g_core[i];
    __syncthreads();
    int n = blockIdx.x * 8 + (tid >> 5);
    int f = tid & 31;
    float s = 0.f;
#pragma unroll
    for (int e = 0; e < DV; ++e) s += nv1[n * DV + e] * sc[e * DV + f];
    g_aT[f * NV + n] = s;
}

// ========== K1c: bf16 hi/lo pre-split of nv2 and aT (logit GEMM operands) ==========
__global__ void k_split(const float* __restrict__ nv2) {
    int idx = blockIdx.x * 256 + threadIdx.x;
    if (idx < NV * DV) {
        float v = nv2[idx];
        __nv_bfloat16 h = __float2bfloat16_rn(v);
        g_A2h[idx] = h;
        g_A2l[idx] = __float2bfloat16_rn(v - __bfloat162float(h));
    } else {
        int j = idx - NV * DV;
        float v = g_aT[j];
        __nv_bfloat16 h = __float2bfloat16_rn(v);
        g_aTh[j] = h;
        g_aTl[j] = __float2bfloat16_rn(v - __bfloat162float(h));
    }
}

// ========== K2: HMMA logit GEMM + exp + fp16 store + colsum ==========
// grid (64 nblk, 64 mblk), CTA 128m x 128n, 256 thr = 8 warps (wm 2 x wn 4).
#define PJ_AH 0
#define PJ_AL 16384
#define PJ_BH 32768
#define PJ_BL 41472
#define PJ_RED 34816          /* after fp16 stage (reuses operand region) */
#define PJ_SMEM 50176

__global__ __launch_bounds__(256) void k_padj_mma() {
    extern __shared__ char sm[];
    uint32_t sb = smem_u32(sm);
    const int tid = threadIdx.x, lane = tid & 31, wid = tid >> 5;
    const int wm = wid & 1;
    const int wn = wid >> 1;
    const int n0 = blockIdx.x * 128;
    const int i0 = blockIdx.y * 128;

#pragma unroll
    for (int l = 0; l < 4; ++l) {
        int idx = tid + l * 256;
        int half = idx >> 9, j = idx & 511;
        int r = j >> 2, kb = j & 3;
        const __nv_bfloat16* src = (half ? g_A2l : g_A2h) + (size_t)(i0 + r) * DV + kb * 8;
        uint32_t slot = (uint32_t)((kb ^ (r & 3)) | (r & 4));
        cp16(sb + (half ? PJ_AL : PJ_AH) + r * 128 + slot * 16, src);
    }
#pragma unroll
    for (int l = 0; l < 4; ++l) {
        int idx = tid + l * 256;
        int half = idx >> 9, j = idx & 511;
        int kr = j >> 4, cb = j & 15;
        const __nv_bfloat16* src = (half ? g_aTl : g_aTh) + (size_t)kr * NV + n0 + cb * 8;
        cp16(sb + (half ? PJ_BL : PJ_BH) + kr * 272 + cb * 16, src);
    }
    asm volatile("cp.async.commit_group;" ::: "memory");
    asm volatile("cp.async.wait_group 0;" ::: "memory");
    __syncthreads();

    float acc[4][4][4];
#pragma unroll
    for (int mt = 0; mt < 4; ++mt)
#pragma unroll
        for (int nt = 0; nt < 4; ++nt)
#pragma unroll
            for (int q = 0; q < 4; ++q) acc[mt][nt][q] = 0.f;

#pragma unroll
    for (int ks = 0; ks < 2; ++ks) {
        uint32_t bh[4][2], bl[4][2];
        int krow = ks * 16 + (lane & 15);
#pragma unroll
        for (int nt = 0; nt < 4; ++nt) {
            uint32_t ba = sb + PJ_BH + krow * 272 + (wn * 32 + nt * 8) * 2;
            ldsm_x2t(bh[nt][0], bh[nt][1], ba);
            ldsm_x2t(bl[nt][0], bl[nt][1], ba + (PJ_BL - PJ_BH));
        }
        int kb = ks * 2 + (lane >> 4);
#pragma unroll
        for (int mt = 0; mt < 4; ++mt) {
            int rr = wm * 64 + mt * 16 + (lane & 15);
            uint32_t slot = (uint32_t)((kb ^ (rr & 3)) | (rr & 4));
            uint32_t aa = sb + PJ_AH + rr * 128 + slot * 16;
            uint32_t ah0, ah1, ah2, ah3, al0, al1, al2, al3;
            ldsm_x4(ah0, ah1, ah2, ah3, aa);
            ldsm_x4(al0, al1, al2, al3, aa + (PJ_AL - PJ_AH));
#pragma unroll
            for (int nt = 0; nt < 4; ++nt) {
                mma16816(acc[mt][nt], ah0, ah1, ah2, ah3, bh[nt][0], bh[nt][1]);
                mma16816(acc[mt][nt], ah0, ah1, ah2, ah3, bl[nt][0], bl[nt][1]);
                mma16816(acc[mt][nt], al0, al1, al2, al3, bh[nt][0], bh[nt][1]);
            }
        }
    }
    __syncthreads();   // operands dead; reuse region for fp16 stage + red

    uint32_t* sth = (uint32_t*)(sm);
    float* red = (float*)(sm + PJ_RED);
    int slot = wm * 8 + (lane >> 2);
    int npb = wn * 16 + (lane & 3);
#pragma unroll
    for (int nt = 0; nt < 4; ++nt) {
        float se = 0.f, so = 0.f;
        int np = npb + nt * 4;
#pragma unroll
        for (int mt = 0; mt < 4; ++mt) {
            float* c = acc[mt][nt];
            int mlo = wm * 64 + mt * 16 + (lane >> 2);
            float p0 = __expf(fmaxf(c[0], 0.f));
            float p1 = __expf(fmaxf(c[1], 0.f));
            float p2 = __expf(fmaxf(c[2], 0.f));
            float p3 = __expf(fmaxf(c[3], 0.f));
            se += p0 + p2; so += p1 + p3;
            __half2 h01 = __floats2half2_rn(p0, p1);
            __half2 h23 = __floats2half2_rn(p2, p3);
            sth[mlo * 68 + np] = *(uint32_t*)&h01;
            sth[(mlo + 8) * 68 + np] = *(uint32_t*)&h23;
        }
        *(float2*)&red[slot * 132 + wn * 32 + nt * 8 + (lane & 3) * 2] = make_float2(se, so);
    }
    __syncthreads();

    size_t wbase = (size_t)i0 * (NV / 2) + (n0 >> 1);
#pragma unroll
    for (int it = 0; it < 8; ++it) {
        int idx = tid + it * 256;
        int row = idx >> 4, cb = idx & 15;
        *(uint4*)&g_Ph32[wbase + (size_t)row * (NV / 2) + cb * 4] = *(uint4*)&sth[row * 68 + cb * 4];
    }
    if (tid < 128) {
        float s = 0.f;
#pragma unroll
        for (int q = 0; q < 16; ++q) s += red[q * 132 + tid];
        g_cspart[blockIdx.y * NV + n0 + tid] = s;
    }
}

// ========== K2b: rowsum reduce -> 4096/rowsum ==========
__global__ void k_rsum() {
    int n = blockIdx.x * 64 + threadIdx.x;
    float s = 0.f;
#pragma unroll
    for (int mb = 0; mb < 64; ++mb) s += g_cspart[mb * NV + n];
    g_rinv[n] = 4096.0f / s;
}

// ========== K3: B[n][r] = x[bc][n][t] * (4096/rowsum[n]) as fp16 hi/lo ==========
__global__ __launch_bounds__(96) void k_xs(const float* __restrict__ x) {
    int n = blockIdx.x;
    int tid = threadIdx.x;
    float inv = g_rinv[n];
    int r0 = tid * 2;
    int bc = r0 / TV, t = r0 - bc * TV;
    const float* xp = x + ((size_t)bc * NV + n) * TV + t;
    float v0 = xp[0] * inv, v1 = xp[1] * inv;
    __half h0 = __float2half_rn(v0), h1 = __float2half_rn(v1);
    float l0 = v0 - __half2float(h0);
    float l1 = v1 - __half2float(h1);
    __half2 hh = __halves2half2(h0, h1);
    __half2 ll = __floats2half2_rn(l0, l1);
    g_Bh32[n * 96 + tid] = *(uint32_t*)&hh;
    g_Bl32[n * 96 + tid] = *(uint32_t*)&ll;
}

// ========== K4: fp16 HMMA GEMM  C[m][r] = sum_n P[m][n]*(xs_hi+xs_lo)[n][r] ==========
// grid (64, 2), 384 thr = 12 warps (2m x 6n). CTA 128m x 192r, k-chunk 64, 3-stage cp.async.
#define G_BH 16384
#define G_BL 41984
#define G_STAGE 67584
#define G_SMEM (3 * G_STAGE)

__device__ __forceinline__ void g3_load(uint32_t sbase, int stage, int i0, size_t kg, int tid) {
    uint32_t S = sbase + stage * G_STAGE;
    const char* pa = (const char*)g_Ph32;
    const char* bh = (const char*)g_Bh32;
    const char* bl = (const char*)g_Bl32;
#pragma unroll
    for (int l = 0; l < 11; ++l) {
        int idx = tid + l * 384;
        if (idx < 1024) {                       // A: 128 rows x 8 chunks, swizzled
            int row = idx >> 3, kb = idx & 7;
            const char* src = pa + ((size_t)(i0 + row) * NV + kg + kb * 8) * 2;
            cp16(S + row * 128 + (((uint32_t)(kb ^ (row & 7))) << 4), src);
        } else if (idx < 2560) {                // B hi: 64 rows x 24 chunks, stride 400
            int j = idx - 1024;
            int kr = j / 24, cb = j % 24;
            cp16(S + G_BH + kr * 400 + cb * 16, bh + (kg + kr) * 384 + cb * 16);
        } else if (idx < 4096) {                // B lo
            int j = idx - 2560;
            int kr = j / 24, cb = j % 24;
            cp16(S + G_BL + kr * 400 + cb * 16, bl + (kg + kr) * 384 + cb * 16);
        }
    }
    asm volatile("cp.async.commit_group;" ::: "memory");
}

__global__ __launch_bounds__(384, 1) void k_gemm4() {
    extern __shared__ char sm[];
    uint32_t sbase = smem_u32(sm);
    const int tid = threadIdx.x, lane = tid & 31, wid = tid >> 5;
    const int wm = wid & 1;           // 64-row half
    const int wn = wid >> 1;          // 0..5 -> 32-col slice
    const int i0 = blockIdx.x * 128;
    const size_t k0 = (size_t)blockIdx.y * 4096;

    float acc[4][4][4];
#pragma unroll
    for (int mt = 0; mt < 4; ++mt)
#pragma unroll
        for (int nt = 0; nt < 4; ++nt)
#pragma unroll
            for (int q = 0; q < 4; ++q) acc[mt][nt][q] = 0.f;

    g3_load(sbase, 0, i0, k0, tid);
    g3_load(sbase, 1, i0, k0 + 64, tid);

    for (int c = 0; c < 64; ++c) {
        if (c + 2 < 64) g3_load(sbase, (c + 2) % 3, i0, k0 + (size_t)(c + 2) * 64, tid);
        else asm volatile("cp.async.commit_group;" ::: "memory");
        asm volatile("cp.async.wait_group 2;" ::: "memory");
        __syncthreads();

        uint32_t A = sbase + (c % 3) * G_STAGE;
        uint32_t B = A + G_BH;
#pragma unroll
        for (int ks = 0; ks < 4; ++ks) {
            uint32_t bh[2][4], bl[2][4];
            int krow = ks * 16 + (lane & 15);
#pragma unroll
            for (int h = 0; h < 2; ++h) {
                uint32_t ba = B + krow * 400 + (wn * 32 + h * 16 + (lane >> 4) * 8) * 2;
                ldsm_x4t(bh[h][0], bh[h][1], bh[h][2], bh[h][3], ba);
                ldsm_x4t(bl[h][0], bl[h][1], bl[h][2], bl[h][3], ba + (G_BL - G_BH));
            }
            int kb = ks * 2 + (lane >> 4);
#pragma unroll
            for (int mt = 0; mt < 4; ++mt) {
                int rr = wm * 64 + mt * 16 + (lane & 15);
                uint32_t aa = A + rr * 128 + (((uint32_t)(kb ^ (rr & 7))) << 4);
                uint32_t a0, a1, a2, a3;
                ldsm_x4(a0, a1, a2, a3, aa);
#pragma unroll
                for (int h = 0; h < 2; ++h)
#pragma unroll
                    for (int s = 0; s < 2; ++s) {
                        int nt = h * 2 + s;
                        mma16816h(acc[mt][nt], a0, a1, a2, a3, bh[h][2 * s], bh[h][2 * s + 1]);
                        mma16816h(acc[mt][nt], a0, a1, a2, a3, bl[h][2 * s], bl[h][2 * s + 1]);
                    }
            }
        }
        __syncthreads();
    }

    float* outp = g_part2 + (size_t)blockIdx.y * NV * RV;
#pragma unroll
    for (int mt = 0; mt < 4; ++mt) {
#pragma unroll
        for (int nt = 0; nt < 4; ++nt) {
            int m = i0 + wm * 64 + mt * 16 + (lane >> 2);
            int r = wn * 32 + nt * 8 + (lane & 3) * 2;
            *(float2*)&outp[(size_t)m * RV + r] = make_float2(acc[mt][nt][0], acc[mt][nt][1]);
            *(float2*)&outp[(size_t)(m + 8) * RV + r] = make_float2(acc[mt][nt][2], acc[mt][nt][3]);
        }
    }
}

// ========== K5: reduce 2 split-K partials (undo 4096 scale), scatter ==========
__global__ void k_out2(float* __restrict__ out) {
    int idx = blockIdx.x * 256 + threadIdx.x;
    if (idx >= NV * RV) return;
    int m = idx / RV, r = idx - m * RV;
    float v = (g_part2[idx] + g_part2[(size_t)NV * RV + idx]) * (1.0f / 4096.0f);
    int bc = r / TV, t = r - bc * TV;
    out[((size_t)bc * NV + m) * TV + t] = v;
}

extern "C" void kernel_launch(void* const* d_in, const int* in_sizes, int n_in,
                              void* d_out, int out_size) {
    const float* x    = (const float*)d_in[0];
    const float* nv1  = (const float*)d_in[1];
    const float* nv2  = (const float*)d_in[2];
    const float* tvv  = (const float*)d_in[3];
    const float* kk   = (const float*)d_in[4];
    const int*   tind = (const int*)d_in[5];
    float* out = (float*)d_out;

    cudaFuncSetAttribute(k_gemm4, cudaFuncAttributeMaxDynamicSharedMemorySize, G_SMEM);
    cudaFuncSetAttribute(k_padj_mma, cudaFuncAttributeMaxDynamicSharedMemorySize, PJ_SMEM);

    k_core<<<1, 1024>>>(tvv, kk, tind);
    k_amat<<<NV / 8, 256>>>(nv1);
    k_split<<<2 * NV * DV / 256, 256>>>(nv2);
    k_padj_mma<<<dim3(64, 64), 256, PJ_SMEM>>>();
    k_rsum<<<NV / 64, 64>>>();
    k_xs<<<NV, 96>>>(x);
    k_gemm4<<<dim3(64, 2), 384, G_SMEM>>>();
    k_out2<<<(NV * RV + 255) / 256, 256>>>(out);
}

// round 8
// speedup vs baseline: 2.1685x; 1.2919x over previous
#include <cuda_runtime.h>
#include <cuda_bf16.h>
#include <cuda_fp16.h>
#include <cstdint>

#define NV 8192
#define DV 32
#define TV 12
#define RV 192   /* B*C*T = 2*8*12 */

typedef unsigned long long ull;

// ---------------- device scratch (no cudaMalloc anywhere) ----------------
__device__ float    g_core[DV * DV];
__device__ float    g_aT[DV * NV];                    // a transposed [f][n]
__device__ __nv_bfloat16 g_A2h[NV * DV];              // nv2 hi bf16 [m][k]
__device__ __nv_bfloat16 g_A2l[NV * DV];              // nv2 lo
__device__ __nv_bfloat16 g_aTh[DV * NV];              // aT hi bf16 [k][n]
__device__ __nv_bfloat16 g_aTl[DV * NV];              // aT lo
__device__ uint32_t g_Ph32[(size_t)NV * NV / 2];      // Pt fp16 pairs [m][n], 128MB
__device__ uint32_t g_Bh32[NV * 96];                  // xs fp16 pairs [n][r] (x4096)
__device__ float    g_cspart[64 * NV];                // column-sum partials per m-block
__device__ float    g_rinv[NV];                       // 4096/rowsum
__device__ float    g_part2[2ULL * NV * RV];          // split-k partials fp32

// ---------------- mma / ldmatrix / cp.async helpers (plain sm_80+ PTX) ----------------
__device__ __forceinline__ uint32_t smem_u32(const void* p) {
    uint32_t a;
    asm("{ .reg .u64 t; cvta.to.shared.u64 t, %1; cvt.u32.u64 %0, t; }" : "=r"(a) : "l"(p));
    return a;
}
__device__ __forceinline__ void ldsm_x4(uint32_t &r0, uint32_t &r1, uint32_t &r2, uint32_t &r3,
                                        uint32_t a) {
    asm volatile("ldmatrix.sync.aligned.m8n8.x4.shared.b16 {%0,%1,%2,%3}, [%4];"
                 : "=r"(r0), "=r"(r1), "=r"(r2), "=r"(r3) : "r"(a));
}
__device__ __forceinline__ void ldsm_x4t(uint32_t &r0, uint32_t &r1, uint32_t &r2, uint32_t &r3,
                                         uint32_t a) {
    asm volatile("ldmatrix.sync.aligned.m8n8.x4.trans.shared.b16 {%0,%1,%2,%3}, [%4];"
                 : "=r"(r0), "=r"(r1), "=r"(r2), "=r"(r3) : "r"(a));
}
__device__ __forceinline__ void ldsm_x2t(uint32_t &r0, uint32_t &r1, uint32_t a) {
    asm volatile("ldmatrix.sync.aligned.m8n8.x2.trans.shared.b16 {%0,%1}, [%2];"
                 : "=r"(r0), "=r"(r1) : "r"(a));
}
__device__ __forceinline__ void mma16816(float* c, uint32_t a0, uint32_t a1, uint32_t a2,
                                         uint32_t a3, uint32_t b0, uint32_t b1) {
    asm volatile(
        "mma.sync.aligned.m16n8k16.row.col.f32.bf16.bf16.f32 "
        "{%0,%1,%2,%3}, {%4,%5,%6,%7}, {%8,%9}, {%0,%1,%2,%3};"
        : "+f"(c[0]), "+f"(c[1]), "+f"(c[2]), "+f"(c[3])
        : "r"(a0), "r"(a1), "r"(a2), "r"(a3), "r"(b0), "r"(b1));
}
__device__ __forceinline__ void mma16816h(float* c, uint32_t a0, uint32_t a1, uint32_t a2,
                                          uint32_t a3, uint32_t b0, uint32_t b1) {
    asm volatile(
        "mma.sync.aligned.m16n8k16.row.col.f32.f16.f16.f32 "
        "{%0,%1,%2,%3}, {%4,%5,%6,%7}, {%8,%9}, {%0,%1,%2,%3};"
        : "+f"(c[0]), "+f"(c[1]), "+f"(c[2]), "+f"(c[3])
        : "r"(a0), "r"(a1), "r"(a2), "r"(a3), "r"(b0), "r"(b1));
}
__device__ __forceinline__ void cp16(uint32_t d, const void* s) {
    asm volatile("cp.async.cg.shared.global [%0], [%1], 16;" :: "r"(d), "l"(s) : "memory");
}

// ========== K1a: core[e][f] = sum_d tv[d]*k[d][e][f] ==========
__global__ void k_core(const float* __restrict__ timevec, const float* __restrict__ kk,
                       const int* __restrict__ tind) {
    int e = threadIdx.x >> 5, f = threadIdx.x & 31;
    int ti = tind[0];
    float s = 0.f;
#pragma unroll
    for (int d = 0; d < DV; ++d) s += timevec[ti * DV + d] * kk[(d * DV + e) * DV + f];
    g_core[e * DV + f] = s;
}

// ========== K1b: aT[f][n] = sum_e nv1[n][e]*core[e][f] ==========
__global__ void k_amat(const float* __restrict__ nv1) {
    __shared__ float sc[DV * DV];
    int tid = threadIdx.x;
    for (int i = tid; i < DV * DV; i += 256) sc[i] = g_core[i];
    __syncthreads();
    int n = blockIdx.x * 8 + (tid >> 5);
    int f = tid & 31;
    float s = 0.f;
#pragma unroll
    for (int e = 0; e < DV; ++e) s += nv1[n * DV + e] * sc[e * DV + f];
    g_aT[f * NV + n] = s;
}

// ========== K1c: bf16 hi/lo pre-split of nv2 and aT (logit GEMM operands) ==========
__global__ void k_split(const float* __restrict__ nv2) {
    int idx = blockIdx.x * 256 + threadIdx.x;
    if (idx < NV * DV) {
        float v = nv2[idx];
        __nv_bfloat16 h = __float2bfloat16_rn(v);
        g_A2h[idx] = h;
        g_A2l[idx] = __float2bfloat16_rn(v - __bfloat162float(h));
    } else {
        int j = idx - NV * DV;
        float v = g_aT[j];
        __nv_bfloat16 h = __float2bfloat16_rn(v);
        g_aTh[j] = h;
        g_aTl[j] = __float2bfloat16_rn(v - __bfloat162float(h));
    }
}

// ========== K2: HMMA logit GEMM + exp + fp16 store + colsum ==========
// grid (64 nblk, 64 mblk), CTA 128m x 128n, 256 thr = 8 warps (wm 2 x wn 4).
#define PJ_AH 0
#define PJ_AL 16384
#define PJ_BH 32768
#define PJ_BL 41472
#define PJ_RED 34816          /* after fp16 stage (reuses operand region) */
#define PJ_SMEM 50176

__global__ __launch_bounds__(256, 3) void k_padj_mma() {
    extern __shared__ char sm[];
    uint32_t sb = smem_u32(sm);
    const int tid = threadIdx.x, lane = tid & 31, wid = tid >> 5;
    const int wm = wid & 1;
    const int wn = wid >> 1;
    const int n0 = blockIdx.x * 128;
    const int i0 = blockIdx.y * 128;

#pragma unroll
    for (int l = 0; l < 4; ++l) {
        int idx = tid + l * 256;
        int half = idx >> 9, j = idx & 511;
        int r = j >> 2, kb = j & 3;
        const __nv_bfloat16* src = (half ? g_A2l : g_A2h) + (size_t)(i0 + r) * DV + kb * 8;
        uint32_t slot = (uint32_t)((kb ^ (r & 3)) | (r & 4));
        cp16(sb + (half ? PJ_AL : PJ_AH) + r * 128 + slot * 16, src);
    }
#pragma unroll
    for (int l = 0; l < 4; ++l) {
        int idx = tid + l * 256;
        int half = idx >> 9, j = idx & 511;
        int kr = j >> 4, cb = j & 15;
        const __nv_bfloat16* src = (half ? g_aTl : g_aTh) + (size_t)kr * NV + n0 + cb * 8;
        cp16(sb + (half ? PJ_BL : PJ_BH) + kr * 272 + cb * 16, src);
    }
    asm volatile("cp.async.commit_group;" ::: "memory");
    asm volatile("cp.async.wait_group 0;" ::: "memory");
    __syncthreads();

    float acc[4][4][4];
#pragma unroll
    for (int mt = 0; mt < 4; ++mt)
#pragma unroll
        for (int nt = 0; nt < 4; ++nt)
#pragma unroll
            for (int q = 0; q < 4; ++q) acc[mt][nt][q] = 0.f;

#pragma unroll
    for (int ks = 0; ks < 2; ++ks) {
        uint32_t bh[4][2], bl[4][2];
        int krow = ks * 16 + (lane & 15);
#pragma unroll
        for (int nt = 0; nt < 4; ++nt) {
            uint32_t ba = sb + PJ_BH + krow * 272 + (wn * 32 + nt * 8) * 2;
            ldsm_x2t(bh[nt][0], bh[nt][1], ba);
            ldsm_x2t(bl[nt][0], bl[nt][1], ba + (PJ_BL - PJ_BH));
        }
        int kb = ks * 2 + (lane >> 4);
#pragma unroll
        for (int mt = 0; mt < 4; ++mt) {
            int rr = wm * 64 + mt * 16 + (lane & 15);
            uint32_t slot = (uint32_t)((kb ^ (rr & 3)) | (rr & 4));
            uint32_t aa = sb + PJ_AH + rr * 128 + slot * 16;
            uint32_t ah0, ah1, ah2, ah3, al0, al1, al2, al3;
            ldsm_x4(ah0, ah1, ah2, ah3, aa);
            ldsm_x4(al0, al1, al2, al3, aa + (PJ_AL - PJ_AH));
#pragma unroll
            for (int nt = 0; nt < 4; ++nt) {
                mma16816(acc[mt][nt], ah0, ah1, ah2, ah3, bh[nt][0], bh[nt][1]);
                mma16816(acc[mt][nt], ah0, ah1, ah2, ah3, bl[nt][0], bl[nt][1]);
                mma16816(acc[mt][nt], al0, al1, al2, al3, bh[nt][0], bh[nt][1]);
            }
        }
    }
    __syncthreads();   // operands dead; reuse region for fp16 stage + red

    uint32_t* sth = (uint32_t*)(sm);
    float* red = (float*)(sm + PJ_RED);
    int slot = wm * 8 + (lane >> 2);
    int npb = wn * 16 + (lane & 3);
#pragma unroll
    for (int nt = 0; nt < 4; ++nt) {
        float se = 0.f, so = 0.f;
        int np = npb + nt * 4;
#pragma unroll
        for (int mt = 0; mt < 4; ++mt) {
            float* c = acc[mt][nt];
            int mlo = wm * 64 + mt * 16 + (lane >> 2);
            float p0 = __expf(fmaxf(c[0], 0.f));
            float p1 = __expf(fmaxf(c[1], 0.f));
            float p2 = __expf(fmaxf(c[2], 0.f));
            float p3 = __expf(fmaxf(c[3], 0.f));
            se += p0 + p2; so += p1 + p3;
            __half2 h01 = __floats2half2_rn(p0, p1);
            __half2 h23 = __floats2half2_rn(p2, p3);
            sth[mlo * 68 + np] = *(uint32_t*)&h01;
            sth[(mlo + 8) * 68 + np] = *(uint32_t*)&h23;
        }
        *(float2*)&red[slot * 132 + wn * 32 + nt * 8 + (lane & 3) * 2] = make_float2(se, so);
    }
    __syncthreads();

    size_t wbase = (size_t)i0 * (NV / 2) + (n0 >> 1);
#pragma unroll
    for (int it = 0; it < 8; ++it) {
        int idx = tid + it * 256;
        int row = idx >> 4, cb = idx & 15;
        *(uint4*)&g_Ph32[wbase + (size_t)row * (NV / 2) + cb * 4] = *(uint4*)&sth[row * 68 + cb * 4];
    }
    if (tid < 128) {
        float s = 0.f;
#pragma unroll
        for (int q = 0; q < 16; ++q) s += red[q * 132 + tid];
        g_cspart[blockIdx.y * NV + n0 + tid] = s;
    }
}

// ========== K2b: rowsum reduce -> 4096/rowsum ==========
__global__ void k_rsum() {
    int n = blockIdx.x * 64 + threadIdx.x;
    float s = 0.f;
#pragma unroll
    for (int mb = 0; mb < 64; ++mb) s += g_cspart[mb * NV + n];
    g_rinv[n] = 4096.0f / s;
}

// ========== K3: B[n][r] = x[bc][n][t] * (4096/rowsum[n]) as single fp16 ==========
__global__ __launch_bounds__(96) void k_xs(const float* __restrict__ x) {
    int n = blockIdx.x;
    int tid = threadIdx.x;
    float inv = g_rinv[n];
    int r0 = tid * 2;
    int bc = r0 / TV, t = r0 - bc * TV;
    const float* xp = x + ((size_t)bc * NV + n) * TV + t;
    __half2 hh = __floats2half2_rn(xp[0] * inv, xp[1] * inv);
    g_Bh32[n * 96 + tid] = *(uint32_t*)&hh;
}

// ========== K4: fp16 HMMA GEMM  C[m][r] = sum_n P[m][n]*xs[n][r] ==========
// grid (64, 2), 384 thr = 12 warps (2m x 6n). CTA 128m x 192r, k-chunk 64, 4-stage cp.async.
#define G_BH 16384
#define G_STAGE (16384 + 25600)   /* 41984 */
#define G_SMEM (4 * G_STAGE)      /* 167936 */

__device__ __forceinline__ void g4_load(uint32_t sbase, int stage, int i0, size_t kg, int tid) {
    uint32_t S = sbase + stage * G_STAGE;
    const char* pa = (const char*)g_Ph32;
    const char* bh = (const char*)g_Bh32;
#pragma unroll
    for (int l = 0; l < 7; ++l) {
        int idx = tid + l * 384;
        if (idx < 1024) {                       // A: 128 rows x 8 chunks, swizzled
            int row = idx >> 3, kb = idx & 7;
            const char* src = pa + ((size_t)(i0 + row) * NV + kg + kb * 8) * 2;
            cp16(S + row * 128 + (((uint32_t)(kb ^ (row & 7))) << 4), src);
        } else if (idx < 2560) {                // B: 64 rows x 24 chunks, stride 400
            int j = idx - 1024;
            int kr = j / 24, cb = j % 24;
            cp16(S + G_BH + kr * 400 + cb * 16, bh + (kg + kr) * 384 + cb * 16);
        }
    }
    asm volatile("cp.async.commit_group;" ::: "memory");
}

__global__ __launch_bounds__(384, 1) void k_gemm4() {
    extern __shared__ char sm[];
    uint32_t sbase = smem_u32(sm);
    const int tid = threadIdx.x, lane = tid & 31, wid = tid >> 5;
    const int wm = wid & 1;           // 64-row half
    const int wn = wid >> 1;          // 0..5 -> 32-col slice
    const int i0 = blockIdx.x * 128;
    const size_t k0 = (size_t)blockIdx.y * 4096;

    float acc[4][4][4];
#pragma unroll
    for (int mt = 0; mt < 4; ++mt)
#pragma unroll
        for (int nt = 0; nt < 4; ++nt)
#pragma unroll
            for (int q = 0; q < 4; ++q) acc[mt][nt][q] = 0.f;

    g4_load(sbase, 0, i0, k0, tid);
    g4_load(sbase, 1, i0, k0 + 64, tid);
    g4_load(sbase, 2, i0, k0 + 128, tid);

    for (int c = 0; c < 64; ++c) {
        if (c + 3 < 64) g4_load(sbase, (c + 3) & 3, i0, k0 + (size_t)(c + 3) * 64, tid);
        else asm volatile("cp.async.commit_group;" ::: "memory");
        asm volatile("cp.async.wait_group 3;" ::: "memory");
        __syncthreads();

        uint32_t A = sbase + (c & 3) * G_STAGE;
        uint32_t B = A + G_BH;
#pragma unroll
        for (int ks = 0; ks < 4; ++ks) {
            uint32_t bh[2][4];
            int krow = ks * 16 + (lane & 15);
#pragma unroll
            for (int h = 0; h < 2; ++h) {
                uint32_t ba = B + krow * 400 + (wn * 32 + h * 16 + (lane >> 4) * 8) * 2;
                ldsm_x4t(bh[h][0], bh[h][1], bh[h][2], bh[h][3], ba);
            }
            int kb = ks * 2 + (lane >> 4);
#pragma unroll
            for (int mt = 0; mt < 4; ++mt) {
                int rr = wm * 64 + mt * 16 + (lane & 15);
                uint32_t aa = A + rr * 128 + (((uint32_t)(kb ^ (rr & 7))) << 4);
                uint32_t a0, a1, a2, a3;
                ldsm_x4(a0, a1, a2, a3, aa);
#pragma unroll
                for (int h = 0; h < 2; ++h)
#pragma unroll
                    for (int s = 0; s < 2; ++s) {
                        int nt = h * 2 + s;
                        mma16816h(acc[mt][nt], a0, a1, a2, a3, bh[h][2 * s], bh[h][2 * s + 1]);
                    }
            }
        }
        __syncthreads();
    }

    float* outp = g_part2 + (size_t)blockIdx.y * NV * RV;
#pragma unroll
    for (int mt = 0; mt < 4; ++mt) {
#pragma unroll
        for (int nt = 0; nt < 4; ++nt) {
            int m = i0 + wm * 64 + mt * 16 + (lane >> 2);
            int r = wn * 32 + nt * 8 + (lane & 3) * 2;
            *(float2*)&outp[(size_t)m * RV + r] = make_float2(acc[mt][nt][0], acc[mt][nt][1]);
            *(float2*)&outp[(size_t)(m + 8) * RV + r] = make_float2(acc[mt][nt][2], acc[mt][nt][3]);
        }
    }
}

// ========== K5: reduce 2 split-K partials (undo 4096 scale), scatter ==========
__global__ void k_out2(float* __restrict__ out) {
    int idx = blockIdx.x * 256 + threadIdx.x;
    if (idx >= NV * RV) return;
    int m = idx / RV, r = idx - m * RV;
    float v = (g_part2[idx] + g_part2[(size_t)NV * RV + idx]) * (1.0f / 4096.0f);
    int bc = r / TV, t = r - bc * TV;
    out[((size_t)bc * NV + m) * TV + t] = v;
}

extern "C" void kernel_launch(void* const* d_in, const int* in_sizes, int n_in,
                              void* d_out, int out_size) {
    const float* x    = (const float*)d_in[0];
    const float* nv1  = (const float*)d_in[1];
    const float* nv2  = (const float*)d_in[2];
    const float* tvv  = (const float*)d_in[3];
    const float* kk   = (const float*)d_in[4];
    const int*   tind = (const int*)d_in[5];
    float* out = (float*)d_out;

    cudaFuncSetAttribute(k_gemm4, cudaFuncAttributeMaxDynamicSharedMemorySize, G_SMEM);
    cudaFuncSetAttribute(k_padj_mma, cudaFuncAttributeMaxDynamicSharedMemorySize, PJ_SMEM);

    k_core<<<1, 1024>>>(tvv, kk, tind);
    k_amat<<<NV / 8, 256>>>(nv1);
    k_split<<<2 * NV * DV / 256, 256>>>(nv2);
    k_padj_mma<<<dim3(64, 64), 256, PJ_SMEM>>>();
    k_rsum<<<NV / 64, 64>>>();
    k_xs<<<NV, 96>>>(x);
    k_gemm4<<<dim3(64, 2), 384, G_SMEM>>>();
    k_out2<<<(NV * RV + 255) / 256, 256>>>(out);
}

// round 9
// speedup vs baseline: 2.1714x; 1.0013x over previous
#include <cuda_runtime.h>
#include <cuda_bf16.h>
#include <cuda_fp16.h>
#include <cstdint>

#define NV 8192
#define DV 32
#define TV 12
#define RV 192   /* B*C*T = 2*8*12 */

typedef unsigned long long ull;

// ---------------- device scratch (no cudaMalloc anywhere) ----------------
__device__ float    g_core[DV * DV];
__device__ float    g_aT[DV * NV];                    // a transposed [f][n]
__device__ __nv_bfloat16 g_A2h[NV * DV];              // nv2 hi bf16 [m][k]
__device__ __nv_bfloat16 g_A2l[NV * DV];              // nv2 lo
__device__ __nv_bfloat16 g_aTh[DV * NV];              // aT hi bf16 [k][n]
__device__ __nv_bfloat16 g_aTl[DV * NV];              // aT lo
__device__ uint32_t g_Ph32[(size_t)NV * NV / 2];      // Pt fp16 pairs [m][n], 128MB
__device__ uint32_t g_Bh32[NV * 96];                  // xs fp16 pairs [n][r] (x4096)
__device__ float    g_cspart[64 * NV];                // column-sum partials per m-block
__device__ float    g_rinv[NV];                       // 4096/rowsum
__device__ float    g_part2[2ULL * NV * RV];          // split-k partials fp32

// ---------------- mma / ldmatrix / cp.async helpers (plain sm_80+ PTX) ----------------
__device__ __forceinline__ uint32_t smem_u32(const void* p) {
    uint32_t a;
    asm("{ .reg .u64 t; cvta.to.shared.u64 t, %1; cvt.u32.u64 %0, t; }" : "=r"(a) : "l"(p));
    return a;
}
__device__ __forceinline__ void ldsm_x4(uint32_t &r0, uint32_t &r1, uint32_t &r2, uint32_t &r3,
                                        uint32_t a) {
    asm volatile("ldmatrix.sync.aligned.m8n8.x4.shared.b16 {%0,%1,%2,%3}, [%4];"
                 : "=r"(r0), "=r"(r1), "=r"(r2), "=r"(r3) : "r"(a));
}
__device__ __forceinline__ void ldsm_x4t(uint32_t &r0, uint32_t &r1, uint32_t &r2, uint32_t &r3,
                                         uint32_t a) {
    asm volatile("ldmatrix.sync.aligned.m8n8.x4.trans.shared.b16 {%0,%1,%2,%3}, [%4];"
                 : "=r"(r0), "=r"(r1), "=r"(r2), "=r"(r3) : "r"(a));
}
__device__ __forceinline__ void ldsm_x2t(uint32_t &r0, uint32_t &r1, uint32_t a) {
    asm volatile("ldmatrix.sync.aligned.m8n8.x2.trans.shared.b16 {%0,%1}, [%2];"
                 : "=r"(r0), "=r"(r1) : "r"(a));
}
__device__ __forceinline__ void mma16816(float* c, uint32_t a0, uint32_t a1, uint32_t a2,
                                         uint32_t a3, uint32_t b0, uint32_t b1) {
    asm volatile(
        "mma.sync.aligned.m16n8k16.row.col.f32.bf16.bf16.f32 "
        "{%0,%1,%2,%3}, {%4,%5,%6,%7}, {%8,%9}, {%0,%1,%2,%3};"
        : "+f"(c[0]), "+f"(c[1]), "+f"(c[2]), "+f"(c[3])
        : "r"(a0), "r"(a1), "r"(a2), "r"(a3), "r"(b0), "r"(b1));
}
__device__ __forceinline__ void mma16816h(float* c, uint32_t a0, uint32_t a1, uint32_t a2,
                                          uint32_t a3, uint32_t b0, uint32_t b1) {
    asm volatile(
        "mma.sync.aligned.m16n8k16.row.col.f32.f16.f16.f32 "
        "{%0,%1,%2,%3}, {%4,%5,%6,%7}, {%8,%9}, {%0,%1,%2,%3};"
        : "+f"(c[0]), "+f"(c[1]), "+f"(c[2]), "+f"(c[3])
        : "r"(a0), "r"(a1), "r"(a2), "r"(a3), "r"(b0), "r"(b1));
}
__device__ __forceinline__ void cp16(uint32_t d, const void* s) {
    asm volatile("cp.async.cg.shared.global [%0], [%1], 16;" :: "r"(d), "l"(s) : "memory");
}

// ========== K1a: core[e][f] = sum_d tv[d]*k[d][e][f] ==========
__global__ void k_core(const float* __restrict__ timevec, const float* __restrict__ kk,
                       const int* __restrict__ tind) {
    int e = threadIdx.x >> 5, f = threadIdx.x & 31;
    int ti = tind[0];
    float s = 0.f;
#pragma unroll
    for (int d = 0; d < DV; ++d) s += timevec[ti * DV + d] * kk[(d * DV + e) * DV + f];
    g_core[e * DV + f] = s;
}

// ========== K1b: aT[f][n] = sum_e nv1[n][e]*core[e][f] ==========
__global__ void k_amat(const float* __restrict__ nv1) {
    __shared__ float sc[DV * DV];
    int tid = threadIdx.x;
    for (int i = tid; i < DV * DV; i += 256) sc[i] = g_core[i];
    __syncthreads();
    int n = blockIdx.x * 8 + (tid >> 5);
    int f = tid & 31;
    float s = 0.f;
#pragma unroll
    for (int e = 0; e < DV; ++e) s += nv1[n * DV + e] * sc[e * DV + f];
    g_aT[f * NV + n] = s;
}

// ========== K1c: bf16 hi/lo pre-split of nv2 and aT (logit GEMM operands) ==========
__global__ void k_split(const float* __restrict__ nv2) {
    int idx = blockIdx.x * 256 + threadIdx.x;
    if (idx < NV * DV) {
        float v = nv2[idx];
        __nv_bfloat16 h = __float2bfloat16_rn(v);
        g_A2h[idx] = h;
        g_A2l[idx] = __float2bfloat16_rn(v - __bfloat162float(h));
    } else {
        int j = idx - NV * DV;
        float v = g_aT[j];
        __nv_bfloat16 h = __float2bfloat16_rn(v);
        g_aTh[j] = h;
        g_aTl[j] = __float2bfloat16_rn(v - __bfloat162float(h));
    }
}

// ========== K2: HMMA logit GEMM + exp + fp16 store + colsum ==========
// grid (64 nblk, 64 mblk), CTA 128m x 128n, 256 thr = 8 warps (wm 2 x wn 4).
#define PJ_AH 0
#define PJ_AL 16384
#define PJ_BH 32768
#define PJ_BL 41472
#define PJ_RED 34816          /* after fp16 stage (reuses operand region) */
#define PJ_SMEM 50176

__global__ __launch_bounds__(256, 3) void k_padj_mma() {
    extern __shared__ char sm[];
    uint32_t sb = smem_u32(sm);
    const int tid = threadIdx.x, lane = tid & 31, wid = tid >> 5;
    const int wm = wid & 1;
    const int wn = wid >> 1;
    const int n0 = blockIdx.x * 128;
    const int i0 = blockIdx.y * 128;

#pragma unroll
    for (int l = 0; l < 4; ++l) {
        int idx = tid + l * 256;
        int half = idx >> 9, j = idx & 511;
        int r = j >> 2, kb = j & 3;
        const __nv_bfloat16* src = (half ? g_A2l : g_A2h) + (size_t)(i0 + r) * DV + kb * 8;
        uint32_t slot = (uint32_t)((kb ^ (r & 3)) | (r & 4));
        cp16(sb + (half ? PJ_AL : PJ_AH) + r * 128 + slot * 16, src);
    }
#pragma unroll
    for (int l = 0; l < 4; ++l) {
        int idx = tid + l * 256;
        int half = idx >> 9, j = idx & 511;
        int kr = j >> 4, cb = j & 15;
        const __nv_bfloat16* src = (half ? g_aTl : g_aTh) + (size_t)kr * NV + n0 + cb * 8;
        cp16(sb + (half ? PJ_BL : PJ_BH) + kr * 272 + cb * 16, src);
    }
    asm volatile("cp.async.commit_group;" ::: "memory");
    asm volatile("cp.async.wait_group 0;" ::: "memory");
    __syncthreads();

    float acc[4][4][4];
#pragma unroll
    for (int mt = 0; mt < 4; ++mt)
#pragma unroll
        for (int nt = 0; nt < 4; ++nt)
#pragma unroll
            for (int q = 0; q < 4; ++q) acc[mt][nt][q] = 0.f;

#pragma unroll
    for (int ks = 0; ks < 2; ++ks) {
        uint32_t bh[4][2], bl[4][2];
        int krow = ks * 16 + (lane & 15);
#pragma unroll
        for (int nt = 0; nt < 4; ++nt) {
            uint32_t ba = sb + PJ_BH + krow * 272 + (wn * 32 + nt * 8) * 2;
            ldsm_x2t(bh[nt][0], bh[nt][1], ba);
            ldsm_x2t(bl[nt][0], bl[nt][1], ba + (PJ_BL - PJ_BH));
        }
        int kb = ks * 2 + (lane >> 4);
#pragma unroll
        for (int mt = 0; mt < 4; ++mt) {
            int rr = wm * 64 + mt * 16 + (lane & 15);
            uint32_t slot = (uint32_t)((kb ^ (rr & 3)) | (rr & 4));
            uint32_t aa = sb + PJ_AH + rr * 128 + slot * 16;
            uint32_t ah0, ah1, ah2, ah3, al0, al1, al2, al3;
            ldsm_x4(ah0, ah1, ah2, ah3, aa);
            ldsm_x4(al0, al1, al2, al3, aa + (PJ_AL - PJ_AH));
#pragma unroll
            for (int nt = 0; nt < 4; ++nt) {
                mma16816(acc[mt][nt], ah0, ah1, ah2, ah3, bh[nt][0], bh[nt][1]);
                mma16816(acc[mt][nt], ah0, ah1, ah2, ah3, bl[nt][0], bl[nt][1]);
                mma16816(acc[mt][nt], al0, al1, al2, al3, bh[nt][0], bh[nt][1]);
            }
        }
    }
    __syncthreads();   // operands dead; reuse region for fp16 stage + red

    uint32_t* sth = (uint32_t*)(sm);
    float* red = (float*)(sm + PJ_RED);
    int slot = wm * 8 + (lane >> 2);
    int npb = wn * 16 + (lane & 3);
#pragma unroll
    for (int nt = 0; nt < 4; ++nt) {
        float se = 0.f, so = 0.f;
        int np = npb + nt * 4;
#pragma unroll
        for (int mt = 0; mt < 4; ++mt) {
            float* c = acc[mt][nt];
            int mlo = wm * 64 + mt * 16 + (lane >> 2);
            float p0 = __expf(fmaxf(c[0], 0.f));
            float p1 = __expf(fmaxf(c[1], 0.f));
            float p2 = __expf(fmaxf(c[2], 0.f));
            float p3 = __expf(fmaxf(c[3], 0.f));
            se += p0 + p2; so += p1 + p3;
            __half2 h01 = __floats2half2_rn(p0, p1);
            __half2 h23 = __floats2half2_rn(p2, p3);
            sth[mlo * 68 + np] = *(uint32_t*)&h01;
            sth[(mlo + 8) * 68 + np] = *(uint32_t*)&h23;
        }
        *(float2*)&red[slot * 132 + wn * 32 + nt * 8 + (lane & 3) * 2] = make_float2(se, so);
    }
    __syncthreads();

    size_t wbase = (size_t)i0 * (NV / 2) + (n0 >> 1);
#pragma unroll
    for (int it = 0; it < 8; ++it) {
        int idx = tid + it * 256;
        int row = idx >> 4, cb = idx & 15;
        *(uint4*)&g_Ph32[wbase + (size_t)row * (NV / 2) + cb * 4] = *(uint4*)&sth[row * 68 + cb * 4];
    }
    if (tid < 128) {
        float s = 0.f;
#pragma unroll
        for (int q = 0; q < 16; ++q) s += red[q * 132 + tid];
        g_cspart[blockIdx.y * NV + n0 + tid] = s;
    }
}

// ========== K2b: rowsum reduce -> 4096/rowsum ==========
__global__ void k_rsum() {
    int n = blockIdx.x * 64 + threadIdx.x;
    float s = 0.f;
#pragma unroll
    for (int mb = 0; mb < 64; ++mb) s += g_cspart[mb * NV + n];
    g_rinv[n] = 4096.0f / s;
}

// ========== K3: B[n][r] = x[bc][n][t] * (4096/rowsum[n]) as single fp16 ==========
__global__ __launch_bounds__(96) void k_xs(const float* __restrict__ x) {
    int n = blockIdx.x;
    int tid = threadIdx.x;
    float inv = g_rinv[n];
    int r0 = tid * 2;
    int bc = r0 / TV, t = r0 - bc * TV;
    const float* xp = x + ((size_t)bc * NV + n) * TV + t;
    __half2 hh = __floats2half2_rn(xp[0] * inv, xp[1] * inv);
    g_Bh32[n * 96 + tid] = *(uint32_t*)&hh;
}

// ========== K4: fp16 HMMA GEMM  C[m][r] = sum_n P[m][n]*xs[n][r] ==========
// grid (64, 2), 384 thr = 12 warps (2m x 6n). CTA 128m x 192r, k-chunk 64, 4-stage cp.async.
#define G_BH 16384
#define G_STAGE (16384 + 25600)   /* 41984 */
#define G_SMEM (4 * G_STAGE)      /* 167936 */

__device__ __forceinline__ void g4_load(uint32_t sbase, int stage, int i0, size_t kg, int tid) {
    uint32_t S = sbase + stage * G_STAGE;
    const char* pa = (const char*)g_Ph32;
    const char* bh = (const char*)g_Bh32;
#pragma unroll
    for (int l = 0; l < 7; ++l) {
        int idx = tid + l * 384;
        if (idx < 1024) {                       // A: 128 rows x 8 chunks, swizzled
            int row = idx >> 3, kb = idx & 7;
            const char* src = pa + ((size_t)(i0 + row) * NV + kg + kb * 8) * 2;
            cp16(S + row * 128 + (((uint32_t)(kb ^ (row & 7))) << 4), src);
        } else if (idx < 2560) {                // B: 64 rows x 24 chunks, stride 400
            int j = idx - 1024;
            int kr = j / 24, cb = j % 24;
            cp16(S + G_BH + kr * 400 + cb * 16, bh + (kg + kr) * 384 + cb * 16);
        }
    }
    asm volatile("cp.async.commit_group;" ::: "memory");
}

__global__ __launch_bounds__(384, 1) void k_gemm4() {
    extern __shared__ char sm[];
    uint32_t sbase = smem_u32(sm);
    const int tid = threadIdx.x, lane = tid & 31, wid = tid >> 5;
    const int wm = wid & 1;           // 64-row half
    const int wn = wid >> 1;          // 0..5 -> 32-col slice
    const int i0 = blockIdx.x * 128;
    const size_t k0 = (size_t)blockIdx.y * 4096;

    float acc[4][4][4];
#pragma unroll
    for (int mt = 0; mt < 4; ++mt)
#pragma unroll
        for (int nt = 0; nt < 4; ++nt)
#pragma unroll
            for (int q = 0; q < 4; ++q) acc[mt][nt][q] = 0.f;

    g4_load(sbase, 0, i0, k0, tid);
    g4_load(sbase, 1, i0, k0 + 64, tid);
    g4_load(sbase, 2, i0, k0 + 128, tid);

    for (int c = 0; c < 64; ++c) {
        if (c + 3 < 64) g4_load(sbase, (c + 3) & 3, i0, k0 + (size_t)(c + 3) * 64, tid);
        else asm volatile("cp.async.commit_group;" ::: "memory");
        asm volatile("cp.async.wait_group 3;" ::: "memory");
        __syncthreads();

        uint32_t A = sbase + (c & 3) * G_STAGE;
        uint32_t B = A + G_BH;
#pragma unroll
        for (int ks = 0; ks < 4; ++ks) {
            uint32_t bh[2][4];
            int krow = ks * 16 + (lane & 15);
#pragma unroll
            for (int h = 0; h < 2; ++h) {
                uint32_t ba = B + krow * 400 + (wn * 32 + h * 16 + (lane >> 4) * 8) * 2;
                ldsm_x4t(bh[h][0], bh[h][1], bh[h][2], bh[h][3], ba);
            }
            int kb = ks * 2 + (lane >> 4);
#pragma unroll
            for (int mt = 0; mt < 4; ++mt) {
                int rr = wm * 64 + mt * 16 + (lane & 15);
                uint32_t aa = A + rr * 128 + (((uint32_t)(kb ^ (rr & 7))) << 4);
                uint32_t a0, a1, a2, a3;
                ldsm_x4(a0, a1, a2, a3, aa);
#pragma unroll
                for (int h = 0; h < 2; ++h)
#pragma unroll
                    for (int s = 0; s < 2; ++s) {
                        int nt = h * 2 + s;
                        mma16816h(acc[mt][nt], a0, a1, a2, a3, bh[h][2 * s], bh[h][2 * s + 1]);
                    }
            }
        }
        __syncthreads();
    }

    float* outp = g_part2 + (size_t)blockIdx.y * NV * RV;
#pragma unroll
    for (int mt = 0; mt < 4; ++mt) {
#pragma unroll
        for (int nt = 0; nt < 4; ++nt) {
            int m = i0 + wm * 64 + mt * 16 + (lane >> 2);
            int r = wn * 32 + nt * 8 + (lane & 3) * 2;
            *(float2*)&outp[(size_t)m * RV + r] = make_float2(acc[mt][nt][0], acc[mt][nt][1]);
            *(float2*)&outp[(size_t)(m + 8) * RV + r] = make_float2(acc[mt][nt][2], acc[mt][nt][3]);
        }
    }
}

// ========== K5: reduce 2 split-K partials (undo 4096 scale), scatter ==========
__global__ void k_out2(float* __restrict__ out) {
    int idx = blockIdx.x * 256 + threadIdx.x;
    if (idx >= NV * RV) return;
    int m = idx / RV, r = idx - m * RV;
    float v = (g_part2[idx] + g_part2[(size_t)NV * RV + idx]) * (1.0f / 4096.0f);
    int bc = r / TV, t = r - bc * TV;
    out[((size_t)bc * NV + m) * TV + t] = v;
}

extern "C" void kernel_launch(void* const* d_in, const int* in_sizes, int n_in,
                              void* d_out, int out_size) {
    const float* x    = (const float*)d_in[0];
    const float* nv1  = (const float*)d_in[1];
    const float* nv2  = (const float*)d_in[2];
    const float* tvv  = (const float*)d_in[3];
    const float* kk   = (const float*)d_in[4];
    const int*   tind = (const int*)d_in[5];
    float* out = (float*)d_out;

    cudaFuncSetAttribute(k_gemm4, cudaFuncAttributeMaxDynamicSharedMemorySize, G_SMEM);
    cudaFuncSetAttribute(k_padj_mma, cudaFuncAttributeMaxDynamicSharedMemorySize, PJ_SMEM);

    k_core<<<1, 1024>>>(tvv, kk, tind);
    k_amat<<<NV / 8, 256>>>(nv1);
    k_split<<<2 * NV * DV / 256, 256>>>(nv2);
    k_padj_mma<<<dim3(64, 64), 256, PJ_SMEM>>>();
    k_rsum<<<NV / 64, 64>>>();
    k_xs<<<NV, 96>>>(x);
    k_gemm4<<<dim3(64, 2), 384, G_SMEM>>>();
    k_out2<<<(NV * RV + 255) / 256, 256>>>(out);
}

// round 10
// speedup vs baseline: 2.1742x; 1.0013x over previous
#include <cuda_runtime.h>
#include <cuda_bf16.h>
#include <cuda_fp16.h>
#include <cstdint>

#define NV 8192
#define DV 32
#define TV 12
#define RV 192   /* B*C*T = 2*8*12 */

typedef unsigned long long ull;

// ---------------- device scratch (no cudaMalloc anywhere) ----------------
__device__ float    g_core[DV * DV];
__device__ float    g_aT[DV * NV];                    // a transposed [f][n]
__device__ __nv_bfloat16 g_A2h[NV * DV];              // nv2 hi bf16 [m][k]
__device__ __nv_bfloat16 g_A2l[NV * DV];              // nv2 lo
__device__ __nv_bfloat16 g_aTh[DV * NV];              // aT hi bf16 [k][n]
__device__ __nv_bfloat16 g_aTl[DV * NV];              // aT lo
__device__ uint32_t g_Ph32[(size_t)NV * NV / 2];      // Pt fp16 pairs [m][n], 128MB
__device__ uint32_t g_Bh32[NV * 96];                  // xs fp16 pairs [n][r] (x4096)
__device__ float    g_cspart[64 * NV];                // column-sum partials per m-block
__device__ float    g_rinv[NV];                       // 4096/rowsum
__device__ float    g_part2[2ULL * NV * RV];          // split-k partials fp32

// ---------------- mma / ldmatrix / cp.async helpers (plain sm_80+ PTX) ----------------
__device__ __forceinline__ uint32_t smem_u32(const void* p) {
    uint32_t a;
    asm("{ .reg .u64 t; cvta.to.shared.u64 t, %1; cvt.u32.u64 %0, t; }" : "=r"(a) : "l"(p));
    return a;
}
__device__ __forceinline__ void ldsm_x4(uint32_t &r0, uint32_t &r1, uint32_t &r2, uint32_t &r3,
                                        uint32_t a) {
    asm volatile("ldmatrix.sync.aligned.m8n8.x4.shared.b16 {%0,%1,%2,%3}, [%4];"
                 : "=r"(r0), "=r"(r1), "=r"(r2), "=r"(r3) : "r"(a));
}
__device__ __forceinline__ void ldsm_x4t(uint32_t &r0, uint32_t &r1, uint32_t &r2, uint32_t &r3,
                                         uint32_t a) {
    asm volatile("ldmatrix.sync.aligned.m8n8.x4.trans.shared.b16 {%0,%1,%2,%3}, [%4];"
                 : "=r"(r0), "=r"(r1), "=r"(r2), "=r"(r3) : "r"(a));
}
__device__ __forceinline__ void ldsm_x2t(uint32_t &r0, uint32_t &r1, uint32_t a) {
    asm volatile("ldmatrix.sync.aligned.m8n8.x2.trans.shared.b16 {%0,%1}, [%2];"
                 : "=r"(r0), "=r"(r1) : "r"(a));
}
__device__ __forceinline__ void mma16816(float* c, uint32_t a0, uint32_t a1, uint32_t a2,
                                         uint32_t a3, uint32_t b0, uint32_t b1) {
    asm volatile(
        "mma.sync.aligned.m16n8k16.row.col.f32.bf16.bf16.f32 "
        "{%0,%1,%2,%3}, {%4,%5,%6,%7}, {%8,%9}, {%0,%1,%2,%3};"
        : "+f"(c[0]), "+f"(c[1]), "+f"(c[2]), "+f"(c[3])
        : "r"(a0), "r"(a1), "r"(a2), "r"(a3), "r"(b0), "r"(b1));
}
__device__ __forceinline__ void mma16816h(float* c, uint32_t a0, uint32_t a1, uint32_t a2,
                                          uint32_t a3, uint32_t b0, uint32_t b1) {
    asm volatile(
        "mma.sync.aligned.m16n8k16.row.col.f32.f16.f16.f32 "
        "{%0,%1,%2,%3}, {%4,%5,%6,%7}, {%8,%9}, {%0,%1,%2,%3};"
        : "+f"(c[0]), "+f"(c[1]), "+f"(c[2]), "+f"(c[3])
        : "r"(a0), "r"(a1), "r"(a2), "r"(a3), "r"(b0), "r"(b1));
}
__device__ __forceinline__ void cp16(uint32_t d, const void* s) {
    asm volatile("cp.async.cg.shared.global [%0], [%1], 16;" :: "r"(d), "l"(s) : "memory");
}

// ========== K1a: core[e][f] = sum_d tv[d]*k[d][e][f] ==========
__global__ void k_core(const float* __restrict__ timevec, const float* __restrict__ kk,
                       const int* __restrict__ tind) {
    int e = threadIdx.x >> 5, f = threadIdx.x & 31;
    int ti = tind[0];
    float s = 0.f;
#pragma unroll
    for (int d = 0; d < DV; ++d) s += timevec[ti * DV + d] * kk[(d * DV + e) * DV + f];
    g_core[e * DV + f] = s;
}

// ========== K1b: aT[f][n] = sum_e nv1[n][e]*core[e][f] ==========
__global__ void k_amat(const float* __restrict__ nv1) {
    __shared__ float sc[DV * DV];
    int tid = threadIdx.x;
    for (int i = tid; i < DV * DV; i += 256) sc[i] = g_core[i];
    __syncthreads();
    int n = blockIdx.x * 8 + (tid >> 5);
    int f = tid & 31;
    float s = 0.f;
#pragma unroll
    for (int e = 0; e < DV; ++e) s += nv1[n * DV + e] * sc[e * DV + f];
    g_aT[f * NV + n] = s;
}

// ========== K1c: bf16 hi/lo pre-split of nv2 and aT (logit GEMM operands) ==========
__global__ void k_split(const float* __restrict__ nv2) {
    int idx = blockIdx.x * 256 + threadIdx.x;
    if (idx < NV * DV) {
        float v = nv2[idx];
        __nv_bfloat16 h = __float2bfloat16_rn(v);
        g_A2h[idx] = h;
        g_A2l[idx] = __float2bfloat16_rn(v - __bfloat162float(h));
    } else {
        int j = idx - NV * DV;
        float v = g_aT[j];
        __nv_bfloat16 h = __float2bfloat16_rn(v);
        g_aTh[j] = h;
        g_aTl[j] = __float2bfloat16_rn(v - __bfloat162float(h));
    }
}

// ========== K2: HMMA logit GEMM + exp + fp16 store + colsum ==========
// grid (64 nblk, 64 mblk), CTA 128m x 128n, 256 thr = 8 warps (wm 2 x wn 4).
#define PJ_AH 0
#define PJ_AL 16384
#define PJ_BH 32768
#define PJ_BL 41472
#define PJ_RED 34816          /* after fp16 stage (reuses operand region) */
#define PJ_SMEM 50176

__global__ __launch_bounds__(256, 3) void k_padj_mma() {
    extern __shared__ char sm[];
    uint32_t sb = smem_u32(sm);
    const int tid = threadIdx.x, lane = tid & 31, wid = tid >> 5;
    const int wm = wid & 1;
    const int wn = wid >> 1;
    const int n0 = blockIdx.x * 128;
    const int i0 = blockIdx.y * 128;

#pragma unroll
    for (int l = 0; l < 4; ++l) {
        int idx = tid + l * 256;
        int half = idx >> 9, j = idx & 511;
        int r = j >> 2, kb = j & 3;
        const __nv_bfloat16* src = (half ? g_A2l : g_A2h) + (size_t)(i0 + r) * DV + kb * 8;
        uint32_t slot = (uint32_t)((kb ^ (r & 3)) | (r & 4));
        cp16(sb + (half ? PJ_AL : PJ_AH) + r * 128 + slot * 16, src);
    }
#pragma unroll
    for (int l = 0; l < 4; ++l) {
        int idx = tid + l * 256;
        int half = idx >> 9, j = idx & 511;
        int kr = j >> 4, cb = j & 15;
        const __nv_bfloat16* src = (half ? g_aTl : g_aTh) + (size_t)kr * NV + n0 + cb * 8;
        cp16(sb + (half ? PJ_BL : PJ_BH) + kr * 272 + cb * 16, src);
    }
    asm volatile("cp.async.commit_group;" ::: "memory");
    asm volatile("cp.async.wait_group 0;" ::: "memory");
    __syncthreads();

    float acc[4][4][4];
#pragma unroll
    for (int mt = 0; mt < 4; ++mt)
#pragma unroll
        for (int nt = 0; nt < 4; ++nt)
#pragma unroll
            for (int q = 0; q < 4; ++q) acc[mt][nt][q] = 0.f;

#pragma unroll
    for (int ks = 0; ks < 2; ++ks) {
        uint32_t bh[4][2], bl[4][2];
        int krow = ks * 16 + (lane & 15);
#pragma unroll
        for (int nt = 0; nt < 4; ++nt) {
            uint32_t ba = sb + PJ_BH + krow * 272 + (wn * 32 + nt * 8) * 2;
            ldsm_x2t(bh[nt][0], bh[nt][1], ba);
            ldsm_x2t(bl[nt][0], bl[nt][1], ba + (PJ_BL - PJ_BH));
        }
        int kb = ks * 2 + (lane >> 4);
#pragma unroll
        for (int mt = 0; mt < 4; ++mt) {
            int rr = wm * 64 + mt * 16 + (lane & 15);
            uint32_t slot = (uint32_t)((kb ^ (rr & 3)) | (rr & 4));
            uint32_t aa = sb + PJ_AH + rr * 128 + slot * 16;
            uint32_t ah0, ah1, ah2, ah3, al0, al1, al2, al3;
            ldsm_x4(ah0, ah1, ah2, ah3, aa);
            ldsm_x4(al0, al1, al2, al3, aa + (PJ_AL - PJ_AH));
#pragma unroll
            for (int nt = 0; nt < 4; ++nt) {
                mma16816(acc[mt][nt], ah0, ah1, ah2, ah3, bh[nt][0], bh[nt][1]);
                mma16816(acc[mt][nt], ah0, ah1, ah2, ah3, bl[nt][0], bl[nt][1]);
                mma16816(acc[mt][nt], al0, al1, al2, al3, bh[nt][0], bh[nt][1]);
            }
        }
    }
    __syncthreads();   // operands dead; reuse region for fp16 stage + red

    uint32_t* sth = (uint32_t*)(sm);
    float* red = (float*)(sm + PJ_RED);
    int slot = wm * 8 + (lane >> 2);
    int npb = wn * 16 + (lane & 3);
#pragma unroll
    for (int nt = 0; nt < 4; ++nt) {
        float se = 0.f, so = 0.f;
        int np = npb + nt * 4;
#pragma unroll
        for (int mt = 0; mt < 4; ++mt) {
            float* c = acc[mt][nt];
            int mlo = wm * 64 + mt * 16 + (lane >> 2);
            float p0 = __expf(fmaxf(c[0], 0.f));
            float p1 = __expf(fmaxf(c[1], 0.f));
            float p2 = __expf(fmaxf(c[2], 0.f));
            float p3 = __expf(fmaxf(c[3], 0.f));
            se += p0 + p2; so += p1 + p3;
            __half2 h01 = __floats2half2_rn(p0, p1);
            __half2 h23 = __floats2half2_rn(p2, p3);
            sth[mlo * 68 + np] = *(uint32_t*)&h01;
            sth[(mlo + 8) * 68 + np] = *(uint32_t*)&h23;
        }
        *(float2*)&red[slot * 132 + wn * 32 + nt * 8 + (lane & 3) * 2] = make_float2(se, so);
    }
    __syncthreads();

    size_t wbase = (size_t)i0 * (NV / 2) + (n0 >> 1);
#pragma unroll
    for (int it = 0; it < 8; ++it) {
        int idx = tid + it * 256;
        int row = idx >> 4, cb = idx & 15;
        *(uint4*)&g_Ph32[wbase + (size_t)row * (NV / 2) + cb * 4] = *(uint4*)&sth[row * 68 + cb * 4];
    }
    if (tid < 128) {
        float s = 0.f;
#pragma unroll
        for (int q = 0; q < 16; ++q) s += red[q * 132 + tid];
        g_cspart[blockIdx.y * NV + n0 + tid] = s;
    }
}

// ========== K2b: rowsum reduce -> 4096/rowsum ==========
__global__ void k_rsum() {
    int n = blockIdx.x * 64 + threadIdx.x;
    float s = 0.f;
#pragma unroll
    for (int mb = 0; mb < 64; ++mb) s += g_cspart[mb * NV + n];
    g_rinv[n] = 4096.0f / s;
}

// ========== K3: B[n][r] = x[bc][n][t] * (4096/rowsum[n]) as single fp16 ==========
__global__ __launch_bounds__(96) void k_xs(const float* __restrict__ x) {
    int n = blockIdx.x;
    int tid = threadIdx.x;
    float inv = g_rinv[n];
    int r0 = tid * 2;
    int bc = r0 / TV, t = r0 - bc * TV;
    const float* xp = x + ((size_t)bc * NV + n) * TV + t;
    __half2 hh = __floats2half2_rn(xp[0] * inv, xp[1] * inv);
    g_Bh32[n * 96 + tid] = *(uint32_t*)&hh;
}

// ========== K4: fp16 HMMA GEMM  C[m][r] = sum_n P[m][n]*xs[n][r] ==========
// grid (64, 2), 384 thr = 12 warps (2m x 6n). CTA 128m x 192r, k-chunk 64, 4-stage cp.async.
#define G_BH 16384
#define G_STAGE (16384 + 25600)   /* 41984 */
#define G_SMEM (4 * G_STAGE)      /* 167936 */

__device__ __forceinline__ void g4_load(uint32_t sbase, int stage, int i0, size_t kg, int tid) {
    uint32_t S = sbase + stage * G_STAGE;
    const char* pa = (const char*)g_Ph32;
    const char* bh = (const char*)g_Bh32;
#pragma unroll
    for (int l = 0; l < 7; ++l) {
        int idx = tid + l * 384;
        if (idx < 1024) {                       // A: 128 rows x 8 chunks, swizzled
            int row = idx >> 3, kb = idx & 7;
            const char* src = pa + ((size_t)(i0 + row) * NV + kg + kb * 8) * 2;
            cp16(S + row * 128 + (((uint32_t)(kb ^ (row & 7))) << 4), src);
        } else if (idx < 2560) {                // B: 64 rows x 24 chunks, stride 400
            int j = idx - 1024;
            int kr = j / 24, cb = j % 24;
            cp16(S + G_BH + kr * 400 + cb * 16, bh + (kg + kr) * 384 + cb * 16);
        }
    }
    asm volatile("cp.async.commit_group;" ::: "memory");
}

__global__ __launch_bounds__(384, 1) void k_gemm4() {
    extern __shared__ char sm[];
    uint32_t sbase = smem_u32(sm);
    const int tid = threadIdx.x, lane = tid & 31, wid = tid >> 5;
    const int wm = wid & 1;           // 64-row half
    const int wn = wid >> 1;          // 0..5 -> 32-col slice
    const int i0 = blockIdx.x * 128;
    const size_t k0 = (size_t)blockIdx.y * 4096;

    float acc[4][4][4];
#pragma unroll
    for (int mt = 0; mt < 4; ++mt)
#pragma unroll
        for (int nt = 0; nt < 4; ++nt)
#pragma unroll
            for (int q = 0; q < 4; ++q) acc[mt][nt][q] = 0.f;

    g4_load(sbase, 0, i0, k0, tid);
    g4_load(sbase, 1, i0, k0 + 64, tid);
    g4_load(sbase, 2, i0, k0 + 128, tid);

    for (int c = 0; c < 64; ++c) {
        if (c + 3 < 64) g4_load(sbase, (c + 3) & 3, i0, k0 + (size_t)(c + 3) * 64, tid);
        else asm volatile("cp.async.commit_group;" ::: "memory");
        asm volatile("cp.async.wait_group 3;" ::: "memory");
        __syncthreads();

        uint32_t A = sbase + (c & 3) * G_STAGE;
        uint32_t B = A + G_BH;
#pragma unroll
        for (int ks = 0; ks < 4; ++ks) {
            uint32_t bh[2][4];
            int krow = ks * 16 + (lane & 15);
#pragma unroll
            for (int h = 0; h < 2; ++h) {
                uint32_t ba = B + krow * 400 + (wn * 32 + h * 16 + (lane >> 4) * 8) * 2;
                ldsm_x4t(bh[h][0], bh[h][1], bh[h][2], bh[h][3], ba);
            }
            int kb = ks * 2 + (lane >> 4);
#pragma unroll
            for (int mt = 0; mt < 4; ++mt) {
                int rr = wm * 64 + mt * 16 + (lane & 15);
                uint32_t aa = A + rr * 128 + (((uint32_t)(kb ^ (rr & 7))) << 4);
                uint32_t a0, a1, a2, a3;
                ldsm_x4(a0, a1, a2, a3, aa);
#pragma unroll
                for (int h = 0; h < 2; ++h)
#pragma unroll
                    for (int s = 0; s < 2; ++s) {
                        int nt = h * 2 + s;
                        mma16816h(acc[mt][nt], a0, a1, a2, a3, bh[h][2 * s], bh[h][2 * s + 1]);
                    }
            }
        }
        __syncthreads();
    }

    float* outp = g_part2 + (size_t)blockIdx.y * NV * RV;
#pragma unroll
    for (int mt = 0; mt < 4; ++mt) {
#pragma unroll
        for (int nt = 0; nt < 4; ++nt) {
            int m = i0 + wm * 64 + mt * 16 + (lane >> 2);
            int r = wn * 32 + nt * 8 + (lane & 3) * 2;
            *(float2*)&outp[(size_t)m * RV + r] = make_float2(acc[mt][nt][0], acc[mt][nt][1]);
            *(float2*)&outp[(size_t)(m + 8) * RV + r] = make_float2(acc[mt][nt][2], acc[mt][nt][3]);
        }
    }
}

// ========== K5: reduce 2 split-K partials (undo 4096 scale), scatter ==========
__global__ void k_out2(float* __restrict__ out) {
    int idx = blockIdx.x * 256 + threadIdx.x;
    if (idx >= NV * RV) return;
    int m = idx / RV, r = idx - m * RV;
    float v = (g_part2[idx] + g_part2[(size_t)NV * RV + idx]) * (1.0f / 4096.0f);
    int bc = r / TV, t = r - bc * TV;
    out[((size_t)bc * NV + m) * TV + t] = v;
}

extern "C" void kernel_launch(void* const* d_in, const int* in_sizes, int n_in,
                              void* d_out, int out_size) {
    const float* x    = (const float*)d_in[0];
    const float* nv1  = (const float*)d_in[1];
    const float* nv2  = (const float*)d_in[2];
    const float* tvv  = (const float*)d_in[3];
    const float* kk   = (const float*)d_in[4];
    const int*   tind = (const int*)d_in[5];
    float* out = (float*)d_out;

    cudaFuncSetAttribute(k_gemm4, cudaFuncAttributeMaxDynamicSharedMemorySize, G_SMEM);
    cudaFuncSetAttribute(k_padj_mma, cudaFuncAttributeMaxDynamicSharedMemorySize, PJ_SMEM);

    k_core<<<1, 1024>>>(tvv, kk, tind);
    k_amat<<<NV / 8, 256>>>(nv1);
    k_split<<<2 * NV * DV / 256, 256>>>(nv2);
    k_padj_mma<<<dim3(64, 64), 256, PJ_SMEM>>>();
    k_rsum<<<NV / 64, 64>>>();
    k_xs<<<NV, 96>>>(x);
    k_gemm4<<<dim3(64, 2), 384, G_SMEM>>>();
    k_out2<<<(NV * RV + 255) / 256, 256>>>(out);
}

// round 11
// speedup vs baseline: 2.1792x; 1.0023x over previous
#include <cuda_runtime.h>
#include <cuda_bf16.h>
#include <cuda_fp16.h>
#include <cstdint>

#define NV 8192
#define DV 32
#define TV 12
#define RV 192   /* B*C*T = 2*8*12 */

typedef unsigned long long ull;

// ---------------- device scratch (no cudaMalloc anywhere) ----------------
__device__ float    g_core[DV * DV];
__device__ float    g_aT[DV * NV];                    // a transposed [f][n]
__device__ __nv_bfloat16 g_A2h[NV * DV];              // nv2 hi bf16 [m][k]
__device__ __nv_bfloat16 g_A2l[NV * DV];              // nv2 lo
__device__ __nv_bfloat16 g_aTh[DV * NV];              // aT hi bf16 [k][n]
__device__ __nv_bfloat16 g_aTl[DV * NV];              // aT lo
__device__ uint32_t g_Ph32[(size_t)NV * NV / 2];      // Pt fp16 pairs [m][n], 128MB
__device__ uint32_t g_Bh32[NV * 96];                  // xs fp16 pairs [n][r] (x4096)
__device__ float    g_cspart[64 * NV];                // column-sum partials per m-block
__device__ float    g_rinv[NV];                       // 4096/rowsum
__device__ float    g_part2[2ULL * NV * RV];          // split-k partials fp32

// ---------------- mma / ldmatrix / cp.async helpers (plain sm_80+ PTX) ----------------
__device__ __forceinline__ uint32_t smem_u32(const void* p) {
    uint32_t a;
    asm("{ .reg .u64 t; cvta.to.shared.u64 t, %1; cvt.u32.u64 %0, t; }" : "=r"(a) : "l"(p));
    return a;
}
__device__ __forceinline__ void ldsm_x4(uint32_t &r0, uint32_t &r1, uint32_t &r2, uint32_t &r3,
                                        uint32_t a) {
    asm volatile("ldmatrix.sync.aligned.m8n8.x4.shared.b16 {%0,%1,%2,%3}, [%4];"
                 : "=r"(r0), "=r"(r1), "=r"(r2), "=r"(r3) : "r"(a));
}
__device__ __forceinline__ void ldsm_x4t(uint32_t &r0, uint32_t &r1, uint32_t &r2, uint32_t &r3,
                                         uint32_t a) {
    asm volatile("ldmatrix.sync.aligned.m8n8.x4.trans.shared.b16 {%0,%1,%2,%3}, [%4];"
                 : "=r"(r0), "=r"(r1), "=r"(r2), "=r"(r3) : "r"(a));
}
__device__ __forceinline__ void ldsm_x2t(uint32_t &r0, uint32_t &r1, uint32_t a) {
    asm volatile("ldmatrix.sync.aligned.m8n8.x2.trans.shared.b16 {%0,%1}, [%2];"
                 : "=r"(r0), "=r"(r1) : "r"(a));
}
__device__ __forceinline__ void mma16816(float* c, uint32_t a0, uint32_t a1, uint32_t a2,
                                         uint32_t a3, uint32_t b0, uint32_t b1) {
    asm volatile(
        "mma.sync.aligned.m16n8k16.row.col.f32.bf16.bf16.f32 "
        "{%0,%1,%2,%3}, {%4,%5,%6,%7}, {%8,%9}, {%0,%1,%2,%3};"
        : "+f"(c[0]), "+f"(c[1]), "+f"(c[2]), "+f"(c[3])
        : "r"(a0), "r"(a1), "r"(a2), "r"(a3), "r"(b0), "r"(b1));
}
__device__ __forceinline__ void mma16816h(float* c, uint32_t a0, uint32_t a1, uint32_t a2,
                                          uint32_t a3, uint32_t b0, uint32_t b1) {
    asm volatile(
        "mma.sync.aligned.m16n8k16.row.col.f32.f16.f16.f32 "
        "{%0,%1,%2,%3}, {%4,%5,%6,%7}, {%8,%9}, {%0,%1,%2,%3};"
        : "+f"(c[0]), "+f"(c[1]), "+f"(c[2]), "+f"(c[3])
        : "r"(a0), "r"(a1), "r"(a2), "r"(a3), "r"(b0), "r"(b1));
}
__device__ __forceinline__ void cp16(uint32_t d, const void* s) {
    asm volatile("cp.async.cg.shared.global [%0], [%1], 16;" :: "r"(d), "l"(s) : "memory");
}

// ========== K1a: core[e][f] = sum_d tv[d]*k[d][e][f] ==========
__global__ void k_core(const float* __restrict__ timevec, const float* __restrict__ kk,
                       const int* __restrict__ tind) {
    int e = threadIdx.x >> 5, f = threadIdx.x & 31;
    int ti = tind[0];
    float s = 0.f;
#pragma unroll
    for (int d = 0; d < DV; ++d) s += timevec[ti * DV + d] * kk[(d * DV + e) * DV + f];
    g_core[e * DV + f] = s;
}

// ========== K1b: aT[f][n] = sum_e nv1[n][e]*core[e][f] ==========
__global__ void k_amat(const float* __restrict__ nv1) {
    __shared__ float sc[DV * DV];
    int tid = threadIdx.x;
    for (int i = tid; i < DV * DV; i += 256) sc[i] = g_core[i];
    __syncthreads();
    int n = blockIdx.x * 8 + (tid >> 5);
    int f = tid & 31;
    float s = 0.f;
#pragma unroll
    for (int e = 0; e < DV; ++e) s += nv1[n * DV + e] * sc[e * DV + f];
    g_aT[f * NV + n] = s;
}

// ========== K1c: bf16 hi/lo pre-split of nv2 and aT (logit GEMM operands) ==========
__global__ void k_split(const float* __restrict__ nv2) {
    int idx = blockIdx.x * 256 + threadIdx.x;
    if (idx < NV * DV) {
        float v = nv2[idx];
        __nv_bfloat16 h = __float2bfloat16_rn(v);
        g_A2h[idx] = h;
        g_A2l[idx] = __float2bfloat16_rn(v - __bfloat162float(h));
    } else {
        int j = idx - NV * DV;
        float v = g_aT[j];
        __nv_bfloat16 h = __float2bfloat16_rn(v);
        g_aTh[j] = h;
        g_aTl[j] = __float2bfloat16_rn(v - __bfloat162float(h));
    }
}

// ========== K2: HMMA logit GEMM + exp + fp16 store + colsum ==========
// grid (64 nblk, 64 mblk), CTA 128m x 128n, 256 thr = 8 warps (wm 2 x wn 4).
#define PJ_AH 0
#define PJ_AL 16384
#define PJ_BH 32768
#define PJ_BL 41472
#define PJ_RED 34816          /* after fp16 stage (reuses operand region) */
#define PJ_SMEM 50176

__global__ __launch_bounds__(256) void k_padj_mma() {
    extern __shared__ char sm[];
    uint32_t sb = smem_u32(sm);
    const int tid = threadIdx.x, lane = tid & 31, wid = tid >> 5;
    const int wm = wid & 1;
    const int wn = wid >> 1;
    const int n0 = blockIdx.x * 128;
    const int i0 = blockIdx.y * 128;

#pragma unroll
    for (int l = 0; l < 4; ++l) {
        int idx = tid + l * 256;
        int half = idx >> 9, j = idx & 511;
        int r = j >> 2, kb = j & 3;
        const __nv_bfloat16* src = (half ? g_A2l : g_A2h) + (size_t)(i0 + r) * DV + kb * 8;
        uint32_t slot = (uint32_t)((kb ^ (r & 3)) | (r & 4));
        cp16(sb + (half ? PJ_AL : PJ_AH) + r * 128 + slot * 16, src);
    }
#pragma unroll
    for (int l = 0; l < 4; ++l) {
        int idx = tid + l * 256;
        int half = idx >> 9, j = idx & 511;
        int kr = j >> 4, cb = j & 15;
        const __nv_bfloat16* src = (half ? g_aTl : g_aTh) + (size_t)kr * NV + n0 + cb * 8;
        cp16(sb + (half ? PJ_BL : PJ_BH) + kr * 272 + cb * 16, src);
    }
    asm volatile("cp.async.commit_group;" ::: "memory");
    asm volatile("cp.async.wait_group 0;" ::: "memory");
    __syncthreads();

    float acc[4][4][4];
#pragma unroll
    for (int mt = 0; mt < 4; ++mt)
#pragma unroll
        for (int nt = 0; nt < 4; ++nt)
#pragma unroll
            for (int q = 0; q < 4; ++q) acc[mt][nt][q] = 0.f;

#pragma unroll
    for (int ks = 0; ks < 2; ++ks) {
        uint32_t bh[4][2], bl[4][2];
        int krow = ks * 16 + (lane & 15);
#pragma unroll
        for (int nt = 0; nt < 4; ++nt) {
            uint32_t ba = sb + PJ_BH + krow * 272 + (wn * 32 + nt * 8) * 2;
            ldsm_x2t(bh[nt][0], bh[nt][1], ba);
            ldsm_x2t(bl[nt][0], bl[nt][1], ba + (PJ_BL - PJ_BH));
        }
        int kb = ks * 2 + (lane >> 4);
#pragma unroll
        for (int mt = 0; mt < 4; ++mt) {
            int rr = wm * 64 + mt * 16 + (lane & 15);
            uint32_t slot = (uint32_t)((kb ^ (rr & 3)) | (rr & 4));
            uint32_t aa = sb + PJ_AH + rr * 128 + slot * 16;
            uint32_t ah0, ah1, ah2, ah3, al0, al1, al2, al3;
            ldsm_x4(ah0, ah1, ah2, ah3, aa);
            ldsm_x4(al0, al1, al2, al3, aa + (PJ_AL - PJ_AH));
#pragma unroll
            for (int nt = 0; nt < 4; ++nt) {
                mma16816(acc[mt][nt], ah0, ah1, ah2, ah3, bh[nt][0], bh[nt][1]);
                mma16816(acc[mt][nt], ah0, ah1, ah2, ah3, bl[nt][0], bl[nt][1]);
                mma16816(acc[mt][nt], al0, al1, al2, al3, bh[nt][0], bh[nt][1]);
            }
        }
    }
    __syncthreads();   // operands dead; reuse region for fp16 stage + red

    uint32_t* sth = (uint32_t*)(sm);
    float* red = (float*)(sm + PJ_RED);
    int slot = wm * 8 + (lane >> 2);
    int npb = wn * 16 + (lane & 3);
#pragma unroll
    for (int nt = 0; nt < 4; ++nt) {
        float se = 0.f, so = 0.f;
        int np = npb + nt * 4;
#pragma unroll
        for (int mt = 0; mt < 4; ++mt) {
            float* c = acc[mt][nt];
            int mlo = wm * 64 + mt * 16 + (lane >> 2);
            float p0 = __expf(fmaxf(c[0], 0.f));
            float p1 = __expf(fmaxf(c[1], 0.f));
            float p2 = __expf(fmaxf(c[2], 0.f));
            float p3 = __expf(fmaxf(c[3], 0.f));
            se += p0 + p2; so += p1 + p3;
            __half2 h01 = __floats2half2_rn(p0, p1);
            __half2 h23 = __floats2half2_rn(p2, p3);
            sth[mlo * 68 + np] = *(uint32_t*)&h01;
            sth[(mlo + 8) * 68 + np] = *(uint32_t*)&h23;
        }
        *(float2*)&red[slot * 132 + wn * 32 + nt * 8 + (lane & 3) * 2] = make_float2(se, so);
    }
    __syncthreads();

    size_t wbase = (size_t)i0 * (NV / 2) + (n0 >> 1);
#pragma unroll
    for (int it = 0; it < 8; ++it) {
        int idx = tid + it * 256;
        int row = idx >> 4, cb = idx & 15;
        *(uint4*)&g_Ph32[wbase + (size_t)row * (NV / 2) + cb * 4] = *(uint4*)&sth[row * 68 + cb * 4];
    }
    if (tid < 128) {
        float s = 0.f;
#pragma unroll
        for (int q = 0; q < 16; ++q) s += red[q * 132 + tid];
        g_cspart[blockIdx.y * NV + n0 + tid] = s;
    }
}

// ========== K2b: rowsum reduce -> 4096/rowsum ==========
__global__ void k_rsum() {
    int n = blockIdx.x * 64 + threadIdx.x;
    float s = 0.f;
#pragma unroll
    for (int mb = 0; mb < 64; ++mb) s += g_cspart[mb * NV + n];
    g_rinv[n] = 4096.0f / s;
}

// ========== K3: B[n][r] = x[bc][n][t] * (4096/rowsum[n]) as fp16 (coalesced) ==========
// 32 n per 256-thr block; smem transpose.
__global__ __launch_bounds__(256) void k_xs(const float* __restrict__ x) {
    __shared__ float sx[32 * 193];     // [nl][r], odd stride
    __shared__ float sinv[32];
    int tid = threadIdx.x;
    int n0 = blockIdx.x * 32;
    if (tid < 32) sinv[tid] = g_rinv[n0 + tid];
#pragma unroll
    for (int bc = 0; bc < 16; ++bc) {
        const float* src = x + ((size_t)bc * NV + n0) * TV;
        for (int i = tid; i < 32 * TV; i += 256) {
            int nl = i / TV, t = i - nl * TV;
            sx[nl * 193 + bc * TV + t] = src[i];
        }
    }
    __syncthreads();
#pragma unroll
    for (int it = 0; it < 12; ++it) {
        int idx = tid + it * 256;          // 3072 = 32 n x 96 pairs
        int nl = idx / 96, rp = idx - nl * 96;
        float inv = sinv[nl];
        __half2 hh = __floats2half2_rn(sx[nl * 193 + 2 * rp] * inv,
                                       sx[nl * 193 + 2 * rp + 1] * inv);
        g_Bh32[(n0 + nl) * 96 + rp] = *(uint32_t*)&hh;
    }
}

// ========== K4: fp16 HMMA GEMM  C[m][r] = sum_n P[m][n]*xs[n][r] ==========
// grid (64, 2), 384 thr = 12 warps (2m x 6n). CTA 128m x 192r, k-chunk 64, 4-stage cp.async.
#define G_BH 16384
#define G_STAGE (16384 + 25600)   /* 41984 */
#define G_SMEM (4 * G_STAGE)      /* 167936 */

__device__ __forceinline__ void g4_load(uint32_t sbase, int stage, int i0, size_t kg, int tid) {
    uint32_t S = sbase + stage * G_STAGE;
    const char* pa = (const char*)g_Ph32;
    const char* bh = (const char*)g_Bh32;
#pragma unroll
    for (int l = 0; l < 7; ++l) {
        int idx = tid + l * 384;
        if (idx < 1024) {                       // A: 128 rows x 8 chunks, swizzled
            int row = idx >> 3, kb = idx & 7;
            const char* src = pa + ((size_t)(i0 + row) * NV + kg + kb * 8) * 2;
            cp16(S + row * 128 + (((uint32_t)(kb ^ (row & 7))) << 4), src);
        } else if (idx < 2560) {                // B: 64 rows x 24 chunks, stride 400
            int j = idx - 1024;
            int kr = j / 24, cb = j % 24;
            cp16(S + G_BH + kr * 400 + cb * 16, bh + (kg + kr) * 384 + cb * 16);
        }
    }
    asm volatile("cp.async.commit_group;" ::: "memory");
}

__global__ __launch_bounds__(384, 1) void k_gemm4() {
    extern __shared__ char sm[];
    uint32_t sbase = smem_u32(sm);
    const int tid = threadIdx.x, lane = tid & 31, wid = tid >> 5;
    const int wm = wid & 1;           // 64-row half
    const int wn = wid >> 1;          // 0..5 -> 32-col slice
    const int i0 = blockIdx.x * 128;
    const size_t k0 = (size_t)blockIdx.y * 4096;

    float acc[4][4][4];
#pragma unroll
    for (int mt = 0; mt < 4; ++mt)
#pragma unroll
        for (int nt = 0; nt < 4; ++nt)
#pragma unroll
            for (int q = 0; q < 4; ++q) acc[mt][nt][q] = 0.f;

    g4_load(sbase, 0, i0, k0, tid);
    g4_load(sbase, 1, i0, k0 + 64, tid);
    g4_load(sbase, 2, i0, k0 + 128, tid);

    for (int c = 0; c < 64; ++c) {
        if (c + 3 < 64) g4_load(sbase, (c + 3) & 3, i0, k0 + (size_t)(c + 3) * 64, tid);
        else asm volatile("cp.async.commit_group;" ::: "memory");
        asm volatile("cp.async.wait_group 3;" ::: "memory");
        __syncthreads();

        uint32_t A = sbase + (c & 3) * G_STAGE;
        uint32_t B = A + G_BH;
#pragma unroll
        for (int ks = 0; ks < 4; ++ks) {
            uint32_t bh[2][4];
            int krow = ks * 16 + (lane & 15);
#pragma unroll
            for (int h = 0; h < 2; ++h) {
                uint32_t ba = B + krow * 400 + (wn * 32 + h * 16 + (lane >> 4) * 8) * 2;
                ldsm_x4t(bh[h][0], bh[h][1], bh[h][2], bh[h][3], ba);
            }
            int kb = ks * 2 + (lane >> 4);
#pragma unroll
            for (int mt = 0; mt < 4; ++mt) {
                int rr = wm * 64 + mt * 16 + (lane & 15);
                uint32_t aa = A + rr * 128 + (((uint32_t)(kb ^ (rr & 7))) << 4);
                uint32_t a0, a1, a2, a3;
                ldsm_x4(a0, a1, a2, a3, aa);
#pragma unroll
                for (int h = 0; h < 2; ++h)
#pragma unroll
                    for (int s = 0; s < 2; ++s) {
                        int nt = h * 2 + s;
                        mma16816h(acc[mt][nt], a0, a1, a2, a3, bh[h][2 * s], bh[h][2 * s + 1]);
                    }
            }
        }
        __syncthreads();
    }

    float* outp = g_part2 + (size_t)blockIdx.y * NV * RV;
#pragma unroll
    for (int mt = 0; mt < 4; ++mt) {
#pragma unroll
        for (int nt = 0; nt < 4; ++nt) {
            int m = i0 + wm * 64 + mt * 16 + (lane >> 2);
            int r = wn * 32 + nt * 8 + (lane & 3) * 2;
            *(float2*)&outp[(size_t)m * RV + r] = make_float2(acc[mt][nt][0], acc[mt][nt][1]);
            *(float2*)&outp[(size_t)(m + 8) * RV + r] = make_float2(acc[mt][nt][2], acc[mt][nt][3]);
        }
    }
}

// ========== K5: reduce 2 split-K partials (undo 4096 scale), 48B/thread ==========
__global__ __launch_bounds__(256) void k_out3(float* __restrict__ out) {
    int bid = blockIdx.x;                    // 512 = 16 bc x 32 m-blocks
    int bc = bid >> 5, mb = bid & 31;
    int m = mb * 256 + threadIdx.x;
    const float* p0 = g_part2 + (size_t)m * RV + bc * TV;
    const float* p1 = p0 + (size_t)NV * RV;
    const float sc = 1.0f / 4096.0f;
    float4 r0 = *(const float4*)p0;
    float4 r1 = *(const float4*)(p0 + 4);
    float4 r2 = *(const float4*)(p0 + 8);
    float4 s0 = *(const float4*)p1;
    float4 s1 = *(const float4*)(p1 + 4);
    float4 s2 = *(const float4*)(p1 + 8);
    r0.x = (r0.x + s0.x) * sc; r0.y = (r0.y + s0.y) * sc;
    r0.z = (r0.z + s0.z) * sc; r0.w = (r0.w + s0.w) * sc;
    r1.x = (r1.x + s1.x) * sc; r1.y = (r1.y + s1.y) * sc;
    r1.z = (r1.z + s1.z) * sc; r1.w = (r1.w + s1.w) * sc;
    r2.x = (r2.x + s2.x) * sc; r2.y = (r2.y + s2.y) * sc;
    r2.z = (r2.z + s2.z) * sc; r2.w = (r2.w + s2.w) * sc;
    float* o = out + ((size_t)bc * NV + m) * TV;
    *(float4*)o = r0;
    *(float4*)(o + 4) = r1;
    *(float4*)(o + 8) = r2;
}

extern "C" void kernel_launch(void* const* d_in, const int* in_sizes, int n_in,
                              void* d_out, int out_size) {
    const float* x    = (const float*)d_in[0];
    const float* nv1  = (const float*)d_in[1];
    const float* nv2  = (const float*)d_in[2];
    const float* tvv  = (const float*)d_in[3];
    const float* kk   = (const float*)d_in[4];
    const int*   tind = (const int*)d_in[5];
    float* out = (float*)d_out;

    cudaFuncSetAttribute(k_gemm4, cudaFuncAttributeMaxDynamicSharedMemorySize, G_SMEM);
    cudaFuncSetAttribute(k_padj_mma, cudaFuncAttributeMaxDynamicSharedMemorySize, PJ_SMEM);

    k_core<<<1, 1024>>>(tvv, kk, tind);
    k_amat<<<NV / 8, 256>>>(nv1);
    k_split<<<2 * NV * DV / 256, 256>>>(nv2);
    k_padj_mma<<<dim3(64, 64), 256, PJ_SMEM>>>();
    k_rsum<<<NV / 64, 64>>>();
    k_xs<<<NV / 32, 256>>>(x);
    k_gemm4<<<dim3(64, 2), 384, G_SMEM>>>();
    k_out3<<<512, 256>>>(out);
}